// round 3
// baseline (speedup 1.0000x reference)
#include <cuda_runtime.h>
#include <math.h>

#define H     24
#define LIMG  2048
#define LIP   512
#define DMOD  3072
#define DIP   1280
#define HD    128
#define LTOT  2560          // LIMG + LIP
#define SCALE 0.08838834764831845f   // 1/sqrt(128)

typedef unsigned long long ull;

// ---------------- packed f32x2 helpers (sm_103a) ----------------
__device__ __forceinline__ ull fma2(ull a, ull b, ull c) {
    ull d;
    asm("fma.rn.f32x2 %0, %1, %2, %3;" : "=l"(d) : "l"(a), "l"(b), "l"(c));
    return d;
}
__device__ __forceinline__ ull mul2(ull a, ull b) {
    ull d;
    asm("mul.rn.f32x2 %0, %1, %2;" : "=l"(d) : "l"(a), "l"(b));
    return d;
}
__device__ __forceinline__ ull pack2(float lo, float hi) {
    ull d;
    asm("mov.b64 %0, {%1, %2};" : "=l"(d) : "f"(lo), "f"(hi));
    return d;
}
__device__ __forceinline__ float2 unpack2(ull a) {
    float lo, hi;
    asm("mov.b64 {%0, %1}, %2;" : "=f"(lo), "=f"(hi) : "l"(a));
    return make_float2(lo, hi);
}

// ---------------- scratch (device globals; no allocs allowed) ----------------
__device__ float g_e[2 * DIP];                 // shift | scale
__device__ float g_ipnorm[LIP * DIP];
__device__ float g_ipk_raw[LIP * DMOD];
__device__ float g_Qn[(size_t)H * LIMG * HD];
__device__ float g_Kall[(size_t)H * LTOT * HD];
__device__ float g_Vall[(size_t)H * LTOT * HD];

// ---------------- stage 1: e = silu(t_emb) @ w_ada^T + b_ada ----------------
__global__ void ada_kernel(const float* __restrict__ t_emb,
                           const float* __restrict__ w_ada,
                           const float* __restrict__ b_ada) {
    int o = blockIdx.x * 8 + (threadIdx.x >> 5);
    int lane = threadIdx.x & 31;
    if (o >= 2 * DIP) return;
    const float* w = w_ada + (size_t)o * DIP;
    float s = 0.f;
    for (int i = lane; i < DIP; i += 32) {
        float t = t_emb[i];
        float si = t / (1.f + expf(-t));
        s += si * w[i];
    }
#pragma unroll
    for (int off = 16; off; off >>= 1) s += __shfl_xor_sync(0xffffffffu, s, off);
    if (lane == 0) g_e[o] = s + b_ada[o];
}

// ---------------- stage 2: AdaLayerNorm on ip_hidden_states ----------------
__global__ void adaln_kernel(const float* __restrict__ ip) {
    int row = blockIdx.x;                   // 0..511
    const float* x = ip + (size_t)row * DIP;
    __shared__ float red1[8], red2[8];
    float s = 0.f, s2 = 0.f;
    for (int i = threadIdx.x; i < DIP; i += 256) {
        float v = x[i];
        s += v; s2 += v * v;
    }
#pragma unroll
    for (int off = 16; off; off >>= 1) {
        s  += __shfl_xor_sync(0xffffffffu, s, off);
        s2 += __shfl_xor_sync(0xffffffffu, s2, off);
    }
    int w = threadIdx.x >> 5, lane = threadIdx.x & 31;
    if (lane == 0) { red1[w] = s; red2[w] = s2; }
    __syncthreads();
    float ts = 0.f, ts2 = 0.f;
#pragma unroll
    for (int i = 0; i < 8; i++) { ts += red1[i]; ts2 += red2[i]; }
    float mu  = ts / DIP;
    float var = ts2 / DIP - mu * mu;
    float inv = rsqrtf(var + 1e-6f);
    for (int i = threadIdx.x; i < DIP; i += 256) {
        float xn = (x[i] - mu) * inv;
        g_ipnorm[(size_t)row * DIP + i] = xn * (1.f + g_e[DIP + i]) + g_e[i];
    }
}

// ---------------- stage 3: ip_key / ip_value GEMMs (512x3072x1280) ----------
__global__ void ip_gemm_kernel(const float* __restrict__ wk,
                               const float* __restrict__ wv) {
    const float* W = blockIdx.z ? wv : wk;
    int bn = blockIdx.x * 64, bm = blockIdx.y * 64;
    __shared__ float As[64][17], Bs[64][17];
    float acc[4][4] = {};
    int tx = threadIdx.x & 15, ty = threadIdx.x >> 4;
    for (int k0 = 0; k0 < DIP; k0 += 16) {
        for (int i = threadIdx.x; i < 64 * 16; i += 256) {
            int rr = i >> 4, cc = i & 15;
            As[rr][cc] = g_ipnorm[(size_t)(bm + rr) * DIP + k0 + cc];
            Bs[rr][cc] = W[(size_t)(bn + rr) * DIP + k0 + cc];
        }
        __syncthreads();
#pragma unroll
        for (int kk = 0; kk < 16; kk++) {
            float a[4], b[4];
#pragma unroll
            for (int i = 0; i < 4; i++) a[i] = As[ty * 4 + i][kk];
#pragma unroll
            for (int j = 0; j < 4; j++) b[j] = Bs[tx * 4 + j][kk];
#pragma unroll
            for (int i = 0; i < 4; i++)
#pragma unroll
                for (int j = 0; j < 4; j++) acc[i][j] = fmaf(a[i], b[j], acc[i][j]);
        }
        __syncthreads();
    }
#pragma unroll
    for (int i = 0; i < 4; i++)
#pragma unroll
        for (int j = 0; j < 4; j++) {
            int m = bm + ty * 4 + i, n = bn + tx * 4 + j;
            if (blockIdx.z == 0) {
                g_ipk_raw[(size_t)m * DMOD + n] = acc[i][j];
            } else {
                int hh = n >> 7, dd = n & 127;
                g_Vall[((size_t)hh * LTOT + LIMG + m) * HD + dd] = acc[i][j];
            }
        }
}

// ---------------- stage 4: RMSNorm q,k + copy v into head-major layout ------
__device__ __forceinline__ float warp_sum(float s) {
#pragma unroll
    for (int off = 16; off; off >>= 1) s += __shfl_xor_sync(0xffffffffu, s, off);
    return s;
}

__global__ void qkv_rms_kernel(const float* __restrict__ q,
                               const float* __restrict__ k,
                               const float* __restrict__ v,
                               const float* __restrict__ gq,
                               const float* __restrict__ gk) {
    int rid = blockIdx.x * 8 + (threadIdx.x >> 5);
    if (rid >= LIMG * H) return;
    int lane = threadIdx.x & 31;
    int l = rid / H, hh = rid % H;
    size_t src = (size_t)l * DMOD + hh * HD + lane * 4;

    // q
    float4 xv = *(const float4*)(q + src);
    float ss = warp_sum(xv.x * xv.x + xv.y * xv.y + xv.z * xv.z + xv.w * xv.w);
    float inv = rsqrtf(ss / 128.f + 1e-6f);
    float4 gv = ((const float4*)gq)[lane];
    float4 o  = { xv.x * inv * gv.x, xv.y * inv * gv.y, xv.z * inv * gv.z, xv.w * inv * gv.w };
    *(float4*)(g_Qn + ((size_t)hh * LIMG + l) * HD + lane * 4) = o;

    // k
    xv = *(const float4*)(k + src);
    ss = warp_sum(xv.x * xv.x + xv.y * xv.y + xv.z * xv.z + xv.w * xv.w);
    inv = rsqrtf(ss / 128.f + 1e-6f);
    gv = ((const float4*)gk)[lane];
    o = make_float4(xv.x * inv * gv.x, xv.y * inv * gv.y, xv.z * inv * gv.z, xv.w * inv * gv.w);
    *(float4*)(g_Kall + ((size_t)hh * LTOT + l) * HD + lane * 4) = o;

    // v (plain copy)
    *(float4*)(g_Vall + ((size_t)hh * LTOT + l) * HD + lane * 4) = *(const float4*)(v + src);
}

__global__ void ipk_rms_kernel(const float* __restrict__ gipk) {
    int rid = blockIdx.x * 8 + (threadIdx.x >> 5);
    if (rid >= LIP * H) return;
    int lane = threadIdx.x & 31;
    int l = rid / H, hh = rid % H;
    float4 xv = *(const float4*)(g_ipk_raw + (size_t)l * DMOD + hh * HD + lane * 4);
    float ss = warp_sum(xv.x * xv.x + xv.y * xv.y + xv.z * xv.z + xv.w * xv.w);
    float inv = rsqrtf(ss / 128.f + 1e-6f);
    float4 gv = ((const float4*)gipk)[lane];
    float4 o  = { xv.x * inv * gv.x, xv.y * inv * gv.y, xv.z * inv * gv.z, xv.w * inv * gv.w };
    *(float4*)(g_Kall + ((size_t)hh * LTOT + LIMG + l) * HD + lane * 4) = o;
}

// ---------------- stage 5: flash attention (fp32x2, M=64, Ktile=32) ---------
// smem floats: Q 64*132, K 32*132, V 32*132, P 64*33
#define ATTN_SMEM_FLOATS (64 * 132 + 32 * 132 + 32 * 132 + 64 * 33)

__global__ void __launch_bounds__(256) attn_kernel(float* __restrict__ out) {
    extern __shared__ float smem[];
    float* Qs = smem;
    float* Ks = Qs + 64 * 132;
    float* Vs = Ks + 32 * 132;
    float* Ps = Vs + 32 * 132;

    const int hh  = blockIdx.y;
    const int q0  = blockIdx.x * 64;
    const int tid = threadIdx.x;
    const int r   = tid >> 2;    // row within tile (0..63)
    const int qg  = tid & 3;     // quarter

    // load + pre-scale Q tile
    const float4* Qb = (const float4*)(g_Qn + ((size_t)hh * LIMG + q0) * HD);
    for (int i = tid; i < 64 * 32; i += 256) {
        int rr = i >> 5, c4 = i & 31;
        float4 v = Qb[rr * 32 + c4];
        v.x *= SCALE; v.y *= SCALE; v.z *= SCALE; v.w *= SCALE;
        ((float4*)(Qs + rr * 132))[c4] = v;
    }

    const float4* Kh = (const float4*)(g_Kall + (size_t)hh * LTOT * HD);
    const float4* Vh = (const float4*)(g_Vall + (size_t)hh * LTOT * HD);

    // register-pipelined K/V tile loads: each thread owns 4 K + 4 V float4s
    float4 kreg[4], vreg[4];
    const int rr0 = tid >> 5, c40 = tid & 31;   // element (tid + t*256): rr = rr0 + t*8

#pragma unroll
    for (int t = 0; t < 4; t++) {
        kreg[t] = Kh[(size_t)(rr0 + t * 8) * 32 + c40];
        vreg[t] = Vh[(size_t)(rr0 + t * 8) * 32 + c40];
    }
#pragma unroll
    for (int t = 0; t < 4; t++) {
        ((float4*)(Ks + (rr0 + t * 8) * 132))[c40] = kreg[t];
        ((float4*)(Vs + (rr0 + t * 8) * 132))[c40] = vreg[t];
    }

    float m = -1e30f, lsum = 0.f;
    ull acc2[16];
#pragma unroll
    for (int j = 0; j < 16; j++) acc2[j] = 0ull;   // bit pattern of (0.f, 0.f)
    __syncthreads();

    for (int kt = 0; kt < LTOT; kt += 32) {
        // prefetch next tile into registers (hides L2 latency behind compute)
        if (kt + 32 < LTOT) {
#pragma unroll
            for (int t = 0; t < 4; t++) {
                kreg[t] = Kh[(size_t)(kt + 32 + rr0 + t * 8) * 32 + c40];
                vreg[t] = Vh[(size_t)(kt + 32 + rr0 + t * 8) * 32 + c40];
            }
        }

        // S: this thread handles keys (j*4 + qg), j=0..7, for row r — packed f32x2
        ull s2[8];
#pragma unroll
        for (int j = 0; j < 8; j++) s2[j] = 0ull;
        const ulonglong2* Qr = (const ulonglong2*)(Qs + r * 132);
        for (int d4 = 0; d4 < 32; d4++) {
            ulonglong2 qv = Qr[d4];
#pragma unroll
            for (int j = 0; j < 8; j++) {
                ulonglong2 kv = ((const ulonglong2*)(Ks + (j * 4 + qg) * 132))[d4];
                s2[j] = fma2(qv.x, kv.x, s2[j]);
                s2[j] = fma2(qv.y, kv.y, s2[j]);
            }
        }
        float s[8];
#pragma unroll
        for (int j = 0; j < 8; j++) {
            float2 t = unpack2(s2[j]);
            s[j] = t.x + t.y;
        }

        // online softmax (4 lanes share row r)
        float mt = s[0];
#pragma unroll
        for (int j = 1; j < 8; j++) mt = fmaxf(mt, s[j]);
        mt = fmaxf(mt, __shfl_xor_sync(0xffffffffu, mt, 1));
        mt = fmaxf(mt, __shfl_xor_sync(0xffffffffu, mt, 2));
        float mnew = fmaxf(m, mt);
        float corr = __expf(m - mnew);
        float ps = 0.f;
#pragma unroll
        for (int j = 0; j < 8; j++) { s[j] = __expf(s[j] - mnew); ps += s[j]; }
        ps += __shfl_xor_sync(0xffffffffu, ps, 1);
        ps += __shfl_xor_sync(0xffffffffu, ps, 2);
        lsum = lsum * corr + ps;
        m = mnew;
        ull cc = pack2(corr, corr);
#pragma unroll
        for (int j = 0; j < 16; j++) acc2[j] = mul2(acc2[j], cc);
#pragma unroll
        for (int j = 0; j < 8; j++) Ps[r * 33 + j * 4 + qg] = s[j];
        __syncwarp();   // Ps row r written only by this warp's 4-lane group

        // O += P @ V ; this thread owns col chunks (j*4+qg)*4..+4 — packed f32x2
        for (int kk = 0; kk < 32; kk++) {
            float p = Ps[r * 33 + kk];
            ull pp = pack2(p, p);
            const ulonglong2* Vr = (const ulonglong2*)(Vs + kk * 132);
#pragma unroll
            for (int j = 0; j < 8; j++) {
                ulonglong2 vv = Vr[j * 4 + qg];
                acc2[2 * j]     = fma2(pp, vv.x, acc2[2 * j]);
                acc2[2 * j + 1] = fma2(pp, vv.y, acc2[2 * j + 1]);
            }
        }
        __syncthreads();  // all reads of Ks/Vs done

        if (kt + 32 < LTOT) {
#pragma unroll
            for (int t = 0; t < 4; t++) {
                ((float4*)(Ks + (rr0 + t * 8) * 132))[c40] = kreg[t];
                ((float4*)(Vs + (rr0 + t * 8) * 132))[c40] = vreg[t];
            }
            __syncthreads();
        }
    }

    float invl = 1.f / lsum;
    float* op = out + (size_t)(q0 + r) * DMOD + hh * HD;
#pragma unroll
    for (int j = 0; j < 8; j++) {
        float2 a = unpack2(acc2[2 * j]);
        float2 b = unpack2(acc2[2 * j + 1]);
        float4 o = { a.x * invl, a.y * invl, b.x * invl, b.y * invl };
        ((float4*)op)[j * 4 + qg] = o;
    }
}

// ---------------- launch -----------------------------------------------------
extern "C" void kernel_launch(void* const* d_in, const int* in_sizes, int n_in,
                              void* d_out, int out_size) {
    const float* ip   = (const float*)d_in[0];
    const float* q    = (const float*)d_in[1];
    const float* k    = (const float*)d_in[2];
    const float* v    = (const float*)d_in[3];
    const float* temb = (const float*)d_in[4];
    const float* wada = (const float*)d_in[5];
    const float* bada = (const float*)d_in[6];
    const float* wk   = (const float*)d_in[7];
    const float* wv   = (const float*)d_in[8];
    const float* gq   = (const float*)d_in[9];
    const float* gk   = (const float*)d_in[10];
    const float* gipk = (const float*)d_in[11];
    float* out = (float*)d_out;

    ada_kernel<<<(2 * DIP + 7) / 8, 256>>>(temb, wada, bada);
    adaln_kernel<<<LIP, 256>>>(ip);
    ip_gemm_kernel<<<dim3(DMOD / 64, LIP / 64, 2), 256>>>(wk, wv);
    qkv_rms_kernel<<<(LIMG * H + 7) / 8, 256>>>(q, k, v, gq, gk);
    ipk_rms_kernel<<<(LIP * H + 7) / 8, 256>>>(gipk);

    int smem_bytes = ATTN_SMEM_FLOATS * (int)sizeof(float);   // 76032
    cudaFuncSetAttribute(attn_kernel, cudaFuncAttributeMaxDynamicSharedMemorySize, smem_bytes);
    attn_kernel<<<dim3(LIMG / 64, H), 256, smem_bytes>>>(out);
}

// round 5
// speedup vs baseline: 6.7543x; 6.7543x over previous
#include <cuda_runtime.h>
#include <cuda_fp16.h>
#include <math.h>
#include <stdint.h>

#define H     24
#define LIMG  2048
#define LIP   512
#define DMOD  3072
#define DIP   1280
#define HD    128
#define LTOT  2560
#define KT    64
#define NIT   (LTOT / KT)       // 40
#define NQT   (LIMG / 128)      // 16
// 1/sqrt(128) * log2(e)  (exp2-based softmax)
#define SCALE2 0.1275174735772347f

// ================= scratch =================
__device__ float  g_e[2 * DIP];
__device__ float  g_ipnorm[LIP * DIP];
__device__ float  g_ipk_raw[LIP * DMOD];
__device__ float  g_Vall[(size_t)H * LTOT * HD];         // fp32 head-major V
__device__ __half g_Qh[(size_t)H * LIMG * HD];           // pre-scaled fp16 Q
__device__ __half g_Kh[(size_t)H * LTOT * HD];           // fp16 K (img+ip)
__device__ __half g_Vth[(size_t)H * HD * LTOT];          // fp16 V transposed [h][d][key]

__device__ __forceinline__ uint32_t s2u(const void* p) {
    uint32_t a;
    asm("{ .reg .u64 t; cvta.to.shared.u64 t, %1; cvt.u32.u64 %0, t; }" : "=r"(a) : "l"(p));
    return a;
}
__device__ __forceinline__ uint32_t pkh(float a, float b) {
    __half2 h = __floats2half2_rn(a, b);
    return *reinterpret_cast<uint32_t*>(&h);
}
__device__ __forceinline__ void mma_f16(float* c, const uint32_t* a, uint32_t b0, uint32_t b1) {
    asm volatile("mma.sync.aligned.m16n8k16.row.col.f32.f16.f16.f32 "
        "{%0,%1,%2,%3}, {%4,%5,%6,%7}, {%8,%9}, {%0,%1,%2,%3};"
        : "+f"(c[0]), "+f"(c[1]), "+f"(c[2]), "+f"(c[3])
        : "r"(a[0]), "r"(a[1]), "r"(a[2]), "r"(a[3]), "r"(b0), "r"(b1));
}
__device__ __forceinline__ void cp16(uint32_t dst, const void* src) {
    asm volatile("cp.async.cg.shared.global [%0], [%1], 16;" :: "r"(dst), "l"(src));
}

// ================= stage 1: ada ================
__global__ void ada_kernel(const float* __restrict__ t_emb,
                           const float* __restrict__ w_ada,
                           const float* __restrict__ b_ada) {
    int o = blockIdx.x * 8 + (threadIdx.x >> 5);
    int lane = threadIdx.x & 31;
    if (o >= 2 * DIP) return;
    const float* w = w_ada + (size_t)o * DIP;
    float s = 0.f;
    for (int i = lane; i < DIP; i += 32) {
        float t = t_emb[i];
        s += (t / (1.f + expf(-t))) * w[i];
    }
#pragma unroll
    for (int off = 16; off; off >>= 1) s += __shfl_xor_sync(0xffffffffu, s, off);
    if (lane == 0) g_e[o] = s + b_ada[o];
}

// ================= stage 2: AdaLN ================
__global__ void adaln_kernel(const float* __restrict__ ip) {
    int row = blockIdx.x;
    const float* x = ip + (size_t)row * DIP;
    __shared__ float red1[8], red2[8];
    float s = 0.f, s2 = 0.f;
    for (int i = threadIdx.x; i < DIP; i += 256) {
        float v = x[i]; s += v; s2 += v * v;
    }
#pragma unroll
    for (int off = 16; off; off >>= 1) {
        s  += __shfl_xor_sync(0xffffffffu, s, off);
        s2 += __shfl_xor_sync(0xffffffffu, s2, off);
    }
    int w = threadIdx.x >> 5, lane = threadIdx.x & 31;
    if (lane == 0) { red1[w] = s; red2[w] = s2; }
    __syncthreads();
    float ts = 0.f, ts2 = 0.f;
#pragma unroll
    for (int i = 0; i < 8; i++) { ts += red1[i]; ts2 += red2[i]; }
    float mu = ts / DIP;
    float inv = rsqrtf(ts2 / DIP - mu * mu + 1e-6f);
    for (int i = threadIdx.x; i < DIP; i += 256) {
        float xn = (x[i] - mu) * inv;
        g_ipnorm[(size_t)row * DIP + i] = xn * (1.f + g_e[DIP + i]) + g_e[i];
    }
}

// ================= stage 3: ip GEMMs (fp32) ================
__global__ void ip_gemm_kernel(const float* __restrict__ wk,
                               const float* __restrict__ wv) {
    const float* W = blockIdx.z ? wv : wk;
    int bn = blockIdx.x * 64, bm = blockIdx.y * 64;
    __shared__ float As[64][17], Bs[64][17];
    float acc[4][4] = {};
    int tx = threadIdx.x & 15, ty = threadIdx.x >> 4;
    for (int k0 = 0; k0 < DIP; k0 += 16) {
        for (int i = threadIdx.x; i < 64 * 16; i += 256) {
            int rr = i >> 4, cc = i & 15;
            As[rr][cc] = g_ipnorm[(size_t)(bm + rr) * DIP + k0 + cc];
            Bs[rr][cc] = W[(size_t)(bn + rr) * DIP + k0 + cc];
        }
        __syncthreads();
#pragma unroll
        for (int kk = 0; kk < 16; kk++) {
            float a[4], b[4];
#pragma unroll
            for (int i = 0; i < 4; i++) a[i] = As[ty * 4 + i][kk];
#pragma unroll
            for (int j = 0; j < 4; j++) b[j] = Bs[tx * 4 + j][kk];
#pragma unroll
            for (int i = 0; i < 4; i++)
#pragma unroll
                for (int j = 0; j < 4; j++) acc[i][j] = fmaf(a[i], b[j], acc[i][j]);
        }
        __syncthreads();
    }
#pragma unroll
    for (int i = 0; i < 4; i++)
#pragma unroll
        for (int j = 0; j < 4; j++) {
            int m = bm + ty * 4 + i, n = bn + tx * 4 + j;
            if (blockIdx.z == 0) {
                g_ipk_raw[(size_t)m * DMOD + n] = acc[i][j];
            } else {
                int hh = n >> 7, dd = n & 127;
                g_Vall[((size_t)hh * LTOT + LIMG + m) * HD + dd] = acc[i][j];
            }
        }
}

// ================= stage 4: RMS + fp16 pack ================
__device__ __forceinline__ float warp_sum(float s) {
#pragma unroll
    for (int off = 16; off; off >>= 1) s += __shfl_xor_sync(0xffffffffu, s, off);
    return s;
}
__device__ __forceinline__ void st_h4(__half* p, float a, float b, float c, float d) {
    uint2 u = { pkh(a, b), pkh(c, d) };
    *reinterpret_cast<uint2*>(p) = u;
}

__global__ void qkv_rms_kernel(const float* __restrict__ q,
                               const float* __restrict__ k,
                               const float* __restrict__ v,
                               const float* __restrict__ gq,
                               const float* __restrict__ gk) {
    int rid = blockIdx.x * 8 + (threadIdx.x >> 5);
    if (rid >= LIMG * H) return;
    int lane = threadIdx.x & 31;
    int l = rid / H, hh = rid % H;
    size_t src = (size_t)l * DMOD + hh * HD + lane * 4;

    float4 xv = *(const float4*)(q + src);
    float inv = rsqrtf(warp_sum(xv.x*xv.x + xv.y*xv.y + xv.z*xv.z + xv.w*xv.w) / 128.f + 1e-6f) * SCALE2;
    float4 gv = ((const float4*)gq)[lane];
    st_h4(g_Qh + ((size_t)hh * LIMG + l) * HD + lane * 4,
          xv.x*inv*gv.x, xv.y*inv*gv.y, xv.z*inv*gv.z, xv.w*inv*gv.w);

    xv = *(const float4*)(k + src);
    inv = rsqrtf(warp_sum(xv.x*xv.x + xv.y*xv.y + xv.z*xv.z + xv.w*xv.w) / 128.f + 1e-6f);
    gv = ((const float4*)gk)[lane];
    st_h4(g_Kh + ((size_t)hh * LTOT + l) * HD + lane * 4,
          xv.x*inv*gv.x, xv.y*inv*gv.y, xv.z*inv*gv.z, xv.w*inv*gv.w);

    *(float4*)(g_Vall + ((size_t)hh * LTOT + l) * HD + lane * 4) = *(const float4*)(v + src);
}

__global__ void ipk_rms_kernel(const float* __restrict__ gipk) {
    int rid = blockIdx.x * 8 + (threadIdx.x >> 5);
    if (rid >= LIP * H) return;
    int lane = threadIdx.x & 31;
    int l = rid / H, hh = rid % H;
    float4 xv = *(const float4*)(g_ipk_raw + (size_t)l * DMOD + hh * HD + lane * 4);
    float inv = rsqrtf(warp_sum(xv.x*xv.x + xv.y*xv.y + xv.z*xv.z + xv.w*xv.w) / 128.f + 1e-6f);
    float4 gv = ((const float4*)gipk)[lane];
    st_h4(g_Kh + ((size_t)hh * LTOT + LIMG + l) * HD + lane * 4,
          xv.x*inv*gv.x, xv.y*inv*gv.y, xv.z*inv*gv.z, xv.w*inv*gv.w);
}

// ================= stage 4b: V transpose to fp16 [h][d][key] ================
__global__ void vt_kernel() {
    extern __shared__ float sm[];               // [128 keys][133]
    int t = blockIdx.x, hh = blockIdx.y, tid = threadIdx.x;
    const float4* vsrc = (const float4*)(g_Vall + ((size_t)hh * LTOT + (size_t)t * 128) * HD);
    for (int i = tid; i < 128 * 32; i += 256) {
        int kr = i >> 5, d4 = i & 31;
        float4 f = vsrc[kr * 32 + d4];
        sm[kr * 133 + d4 * 4 + 0] = f.x;
        sm[kr * 133 + d4 * 4 + 1] = f.y;
        sm[kr * 133 + d4 * 4 + 2] = f.z;
        sm[kr * 133 + d4 * 4 + 3] = f.w;
    }
    __syncthreads();
    for (int j = 0; j < 8; j++) {
        int g = tid + j * 256;                  // 2048 chunks: d = g>>4, kc = g&15
        int d = g >> 4, kc = g & 15;
        float f[8];
#pragma unroll
        for (int i = 0; i < 8; i++) f[i] = sm[(kc * 8 + i) * 133 + d];
        uint4 u = { pkh(f[0], f[1]), pkh(f[2], f[3]), pkh(f[4], f[5]), pkh(f[6], f[7]) };
        *reinterpret_cast<uint4*>(g_Vth + ((size_t)hh * HD + d) * LTOT + (size_t)t * 128 + kc * 8) = u;
    }
}

// ================= stage 5: mma.sync flash attention ========================
// SMEM: Q 128x272B | K 3 bufs of 64x272B | V 3 bufs of 128x144B
#define SQ_OFF  0
#define SK_OFF  34816
#define SK_BUF  17408
#define SV_OFF  (34816 + 3 * 17408)     // 87040
#define SV_BUF  18432
#define ATTN_SMEM (SV_OFF + 3 * SV_BUF) // 142336

__global__ void __launch_bounds__(256, 1) attn_kernel(float* __restrict__ out) {
    extern __shared__ __align__(16) char smem[];
    const uint32_t sb = s2u(smem);
    const int tid = threadIdx.x;
    const int w = tid >> 5, t = tid & 31;
    const int r4 = t >> 2, q4 = t & 3;
    const int hh = blockIdx.y, q0 = blockIdx.x * 128;

    // ---- Q tile load (row stride 272B) ----
    const uint4* qg = (const uint4*)(g_Qh + ((size_t)hh * LIMG + q0) * HD);
    for (int i = tid; i < 2048; i += 256) {
        int rr = i >> 4, cc = i & 15;
        *(uint4*)(smem + SQ_OFF + rr * 272 + cc * 16) = qg[i];
    }

    // ---- issue first 3 K/V tiles via cp.async ----
    const __half* kgb = g_Kh + (size_t)hh * LTOT * HD;
    const __half* vgb = g_Vth + (size_t)hh * HD * LTOT;
#pragma unroll
    for (int pb = 0; pb < 3; pb++) {
        for (int n = 0; n < 4; n++) {
            int i = tid + n * 256;
            int kr = i >> 4, c = i & 15;
            cp16(sb + SK_OFF + pb * SK_BUF + kr * 272 + c * 16,
                 kgb + ((size_t)(pb * KT + kr)) * HD + c * 8);
            int d = i >> 3, c2 = i & 7;
            cp16(sb + SV_OFF + pb * SV_BUF + d * 144 + c2 * 16,
                 vgb + (size_t)d * LTOT + pb * KT + c2 * 8);
        }
        asm volatile("cp.async.commit_group;");
    }
    __syncthreads();   // Q visible

    // ---- Q fragments (held in registers) ----
    uint32_t qa[8][4];
#pragma unroll
    for (int kb = 0; kb < 8; kb++) {
        const char* base = smem + SQ_OFF + (w * 16 + r4) * 272 + (kb * 16 + 2 * q4) * 2;
        qa[kb][0] = *(const uint32_t*)(base);
        qa[kb][1] = *(const uint32_t*)(base + 8 * 272);
        qa[kb][2] = *(const uint32_t*)(base + 16);
        qa[kb][3] = *(const uint32_t*)(base + 8 * 272 + 16);
    }

    float m_lo = -1e30f, m_hi = -1e30f, l_lo = 0.f, l_hi = 0.f;
    float oc[16][4];
#pragma unroll
    for (int n = 0; n < 16; n++)
#pragma unroll
        for (int j = 0; j < 4; j++) oc[n][j] = 0.f;

    for (int it = 0; it < NIT; it++) {
        const int b = it % 3;
        if (it < NIT - 2)      asm volatile("cp.async.wait_group 2;");
        else if (it == NIT - 2) asm volatile("cp.async.wait_group 1;");
        else                    asm volatile("cp.async.wait_group 0;");
        __syncthreads();

        // ---- S = Q @ K^T ----
        float sc[8][4];
#pragma unroll
        for (int n = 0; n < 8; n++)
#pragma unroll
            for (int j = 0; j < 4; j++) sc[n][j] = 0.f;
        const char* Kb = smem + SK_OFF + b * SK_BUF;
#pragma unroll
        for (int kb = 0; kb < 8; kb++) {
#pragma unroll
            for (int nb = 0; nb < 8; nb++) {
                const char* ba = Kb + (nb * 8 + r4) * 272 + (kb * 16 + 2 * q4) * 2;
                uint32_t b0 = *(const uint32_t*)(ba);
                uint32_t b1 = *(const uint32_t*)(ba + 16);
                mma_f16(sc[nb], qa[kb], b0, b1);
            }
        }

        // ---- online softmax (base-2) ----
        float mt_lo = -1e30f, mt_hi = -1e30f;
#pragma unroll
        for (int n = 0; n < 8; n++) {
            mt_lo = fmaxf(mt_lo, fmaxf(sc[n][0], sc[n][1]));
            mt_hi = fmaxf(mt_hi, fmaxf(sc[n][2], sc[n][3]));
        }
        mt_lo = fmaxf(mt_lo, __shfl_xor_sync(0xffffffffu, mt_lo, 1));
        mt_lo = fmaxf(mt_lo, __shfl_xor_sync(0xffffffffu, mt_lo, 2));
        mt_hi = fmaxf(mt_hi, __shfl_xor_sync(0xffffffffu, mt_hi, 1));
        mt_hi = fmaxf(mt_hi, __shfl_xor_sync(0xffffffffu, mt_hi, 2));
        float mn_lo = fmaxf(m_lo, mt_lo), mn_hi = fmaxf(m_hi, mt_hi);
        float co_lo = exp2f(m_lo - mn_lo), co_hi = exp2f(m_hi - mn_hi);
        float ps_lo = 0.f, ps_hi = 0.f;
#pragma unroll
        for (int n = 0; n < 8; n++) {
            sc[n][0] = exp2f(sc[n][0] - mn_lo);
            sc[n][1] = exp2f(sc[n][1] - mn_lo);
            sc[n][2] = exp2f(sc[n][2] - mn_hi);
            sc[n][3] = exp2f(sc[n][3] - mn_hi);
            ps_lo += sc[n][0] + sc[n][1];
            ps_hi += sc[n][2] + sc[n][3];
        }
        ps_lo += __shfl_xor_sync(0xffffffffu, ps_lo, 1);
        ps_lo += __shfl_xor_sync(0xffffffffu, ps_lo, 2);
        ps_hi += __shfl_xor_sync(0xffffffffu, ps_hi, 1);
        ps_hi += __shfl_xor_sync(0xffffffffu, ps_hi, 2);
        l_lo = l_lo * co_lo + ps_lo; m_lo = mn_lo;
        l_hi = l_hi * co_hi + ps_hi; m_hi = mn_hi;
#pragma unroll
        for (int n = 0; n < 16; n++) {
            oc[n][0] *= co_lo; oc[n][1] *= co_lo;
            oc[n][2] *= co_hi; oc[n][3] *= co_hi;
        }

        // ---- P fragments ----
        uint32_t pa[4][4];
#pragma unroll
        for (int kb = 0; kb < 4; kb++) {
            pa[kb][0] = pkh(sc[2*kb][0],   sc[2*kb][1]);
            pa[kb][1] = pkh(sc[2*kb][2],   sc[2*kb][3]);
            pa[kb][2] = pkh(sc[2*kb+1][0], sc[2*kb+1][1]);
            pa[kb][3] = pkh(sc[2*kb+1][2], sc[2*kb+1][3]);
        }

        // ---- O += P @ V ----
        const char* Vb = smem + SV_OFF + b * SV_BUF;
#pragma unroll
        for (int kb = 0; kb < 4; kb++) {
#pragma unroll
            for (int nb = 0; nb < 16; nb++) {
                const char* ba = Vb + (nb * 8 + r4) * 144 + (kb * 16 + 2 * q4) * 2;
                uint32_t b0 = *(const uint32_t*)(ba);
                uint32_t b1 = *(const uint32_t*)(ba + 16);
                mma_f16(oc[nb], pa[kb], b0, b1);
            }
        }
        __syncthreads();   // everyone done reading buf b

        // ---- refill buf b with tile it+3 ----
        if (it + 3 < NIT) {
            for (int n = 0; n < 4; n++) {
                int i = tid + n * 256;
                int kr = i >> 4, c = i & 15;
                cp16(sb + SK_OFF + b * SK_BUF + kr * 272 + c * 16,
                     kgb + ((size_t)((it + 3) * KT + kr)) * HD + c * 8);
                int d = i >> 3, c2 = i & 7;
                cp16(sb + SV_OFF + b * SV_BUF + d * 144 + c2 * 16,
                     vgb + (size_t)d * LTOT + (it + 3) * KT + c2 * 8);
            }
        }
        asm volatile("cp.async.commit_group;");   // keep group count in lockstep
    }

    // ---- epilogue ----
    float il_lo = 1.f / l_lo, il_hi = 1.f / l_hi;
    float* orow_lo = out + (size_t)(q0 + w * 16 + r4) * DMOD + hh * HD + 2 * q4;
    float* orow_hi = orow_lo + (size_t)8 * DMOD;
#pragma unroll
    for (int nb = 0; nb < 16; nb++) {
        float2 vlo = { oc[nb][0] * il_lo, oc[nb][1] * il_lo };
        float2 vhi = { oc[nb][2] * il_hi, oc[nb][3] * il_hi };
        *(float2*)(orow_lo + nb * 8) = vlo;
        *(float2*)(orow_hi + nb * 8) = vhi;
    }
}

// ================= launch =====================================================
extern "C" void kernel_launch(void* const* d_in, const int* in_sizes, int n_in,
                              void* d_out, int out_size) {
    const float* ip   = (const float*)d_in[0];
    const float* q    = (const float*)d_in[1];
    const float* k    = (const float*)d_in[2];
    const float* v    = (const float*)d_in[3];
    const float* temb = (const float*)d_in[4];
    const float* wada = (const float*)d_in[5];
    const float* bada = (const float*)d_in[6];
    const float* wk   = (const float*)d_in[7];
    const float* wv   = (const float*)d_in[8];
    const float* gq   = (const float*)d_in[9];
    const float* gk   = (const float*)d_in[10];
    const float* gipk = (const float*)d_in[11];
    float* out = (float*)d_out;

    ada_kernel<<<(2 * DIP + 7) / 8, 256>>>(temb, wada, bada);
    adaln_kernel<<<LIP, 256>>>(ip);
    ip_gemm_kernel<<<dim3(DMOD / 64, LIP / 64, 2), 256>>>(wk, wv);
    qkv_rms_kernel<<<(LIMG * H + 7) / 8, 256>>>(q, k, v, gq, gk);
    ipk_rms_kernel<<<(LIP * H + 7) / 8, 256>>>(gipk);

    cudaFuncSetAttribute(vt_kernel, cudaFuncAttributeMaxDynamicSharedMemorySize, 128 * 133 * 4);
    vt_kernel<<<dim3(LTOT / 128, H), 256, 128 * 133 * 4>>>();

    cudaFuncSetAttribute(attn_kernel, cudaFuncAttributeMaxDynamicSharedMemorySize, ATTN_SMEM);
    attn_kernel<<<dim3(NQT, H), 256, ATTN_SMEM>>>(out);
}

// round 7
// speedup vs baseline: 13.5570x; 2.0072x over previous
#include <cuda_runtime.h>
#include <cuda_fp16.h>
#include <math.h>
#include <stdint.h>

#define H     24
#define LIMG  2048
#define LIP   512
#define DMOD  3072
#define DIP   1280
#define HD    128
#define LTOT  2560
#define KT    64
#define NIT   (LTOT / KT)       // 40
#define NQT   (LIMG / 128)      // 16
// 1/sqrt(128) * log2(e)  (exp2-based softmax)
#define SCALE2 0.1275174735772347f

// ================= scratch =================
__device__ float  g_e[2 * DIP];
__device__ __half g_ipnorm_h[LIP * DIP];
__device__ __half g_Wh[2 * (size_t)DMOD * DIP];
__device__ float  g_ipk_raw[LIP * DMOD];
__device__ float  g_Vall[(size_t)H * LTOT * HD];         // fp32 head-major V
__device__ __half g_Qh[(size_t)H * LIMG * HD];           // pre-scaled fp16 Q
__device__ __half g_Kh[(size_t)H * LTOT * HD];           // fp16 K (img+ip)
__device__ __half g_Vth[(size_t)H * HD * LTOT];          // fp16 V transposed [h][d][key]

__device__ __forceinline__ uint32_t s2u(const void* p) {
    uint32_t a;
    asm("{ .reg .u64 t; cvta.to.shared.u64 t, %1; cvt.u32.u64 %0, t; }" : "=r"(a) : "l"(p));
    return a;
}
__device__ __forceinline__ uint32_t pkh(float a, float b) {
    __half2 h = __floats2half2_rn(a, b);
    return *reinterpret_cast<uint32_t*>(&h);
}
__device__ __forceinline__ float ex2(float x) {
    float y;
    asm("ex2.approx.f32 %0, %1;" : "=f"(y) : "f"(x));
    return y;
}
__device__ __forceinline__ void mma_f16(float* c, const uint32_t* a, uint32_t b0, uint32_t b1) {
    asm volatile("mma.sync.aligned.m16n8k16.row.col.f32.f16.f16.f32 "
        "{%0,%1,%2,%3}, {%4,%5,%6,%7}, {%8,%9}, {%0,%1,%2,%3};"
        : "+f"(c[0]), "+f"(c[1]), "+f"(c[2]), "+f"(c[3])
        : "r"(a[0]), "r"(a[1]), "r"(a[2]), "r"(a[3]), "r"(b0), "r"(b1));
}
__device__ __forceinline__ void ldsm4(uint32_t* r, uint32_t addr) {
    asm volatile("ldmatrix.sync.aligned.m8n8.x4.shared.b16 {%0,%1,%2,%3}, [%4];"
        : "=r"(r[0]), "=r"(r[1]), "=r"(r[2]), "=r"(r[3]) : "r"(addr));
}
__device__ __forceinline__ void cp16(uint32_t dst, const void* src) {
    asm volatile("cp.async.cg.shared.global [%0], [%1], 16;" :: "r"(dst), "l"(src));
}

// single extern shared symbol for all dynamic-smem kernels
extern __shared__ __align__(16) char dynsm[];

// ================= stage 1: ada ================
__global__ void ada_kernel(const float* __restrict__ t_emb,
                           const float* __restrict__ w_ada,
                           const float* __restrict__ b_ada) {
    int o = blockIdx.x * 8 + (threadIdx.x >> 5);
    int lane = threadIdx.x & 31;
    if (o >= 2 * DIP) return;
    const float* w = w_ada + (size_t)o * DIP;
    float s = 0.f;
    for (int i = lane; i < DIP; i += 32) {
        float t = t_emb[i];
        s += (t / (1.f + expf(-t))) * w[i];
    }
#pragma unroll
    for (int off = 16; off; off >>= 1) s += __shfl_xor_sync(0xffffffffu, s, off);
    if (lane == 0) g_e[o] = s + b_ada[o];
}

// ================= stage 2: AdaLN -> fp16 ================
__global__ void adaln_kernel(const float* __restrict__ ip) {
    int row = blockIdx.x;
    const float* x = ip + (size_t)row * DIP;
    __shared__ float red1[8], red2[8];
    float s = 0.f, s2 = 0.f;
    for (int i = threadIdx.x; i < DIP; i += 256) {
        float v = x[i]; s += v; s2 += v * v;
    }
#pragma unroll
    for (int off = 16; off; off >>= 1) {
        s  += __shfl_xor_sync(0xffffffffu, s, off);
        s2 += __shfl_xor_sync(0xffffffffu, s2, off);
    }
    int w = threadIdx.x >> 5, lane = threadIdx.x & 31;
    if (lane == 0) { red1[w] = s; red2[w] = s2; }
    __syncthreads();
    float ts = 0.f, ts2 = 0.f;
#pragma unroll
    for (int i = 0; i < 8; i++) { ts += red1[i]; ts2 += red2[i]; }
    float mu = ts / DIP;
    float inv = rsqrtf(ts2 / DIP - mu * mu + 1e-6f);
    for (int i = threadIdx.x; i < DIP; i += 256) {
        float xn = (x[i] - mu) * inv;
        g_ipnorm_h[(size_t)row * DIP + i] = __float2half(xn * (1.f + g_e[DIP + i]) + g_e[i]);
    }
}

// ================= stage 2b: weight fp32 -> fp16 ================
__global__ void wconv_kernel(const float* __restrict__ wk, const float* __restrict__ wv) {
    size_t i = ((size_t)blockIdx.x * 256 + threadIdx.x) * 4;
    const float* src = blockIdx.y ? wv : wk;
    __half* dst = g_Wh + (size_t)blockIdx.y * DMOD * DIP;
    float4 f = *(const float4*)(src + i);
    uint2 u = { pkh(f.x, f.y), pkh(f.z, f.w) };
    *(uint2*)(dst + i) = u;
}

// ================= stage 3: ip GEMMs via mma.sync ================
// C[512 x 3072] = ipnorm_h[512 x 1280] @ W[3072 x 1280]^T
// CTA: 128x128, 8 warps (16 rows each), K-step 64, double-buffered cp.async.
// SMEM: A 2x(128x144B) | B 2x(128x144B) = 73728 B
#define GEMM_SMEM 73728

__device__ __forceinline__ void gemm_issue(uint32_t sb, int tid, int bm, int bn,
                                           const __half* A, const __half* W,
                                           int ks, int buf) {
#pragma unroll
    for (int n = 0; n < 4; n++) {
        int i = tid + n * 256;
        int row = i >> 3, c = i & 7;
        cp16(sb + buf * 18432 + row * 144 + c * 16,
             A + (size_t)(bm + row) * DIP + ks * 64 + c * 8);
        cp16(sb + 36864 + buf * 18432 + row * 144 + c * 16,
             W + (size_t)(bn + row) * DIP + ks * 64 + c * 8);
    }
    asm volatile("cp.async.commit_group;");
}

__global__ void __launch_bounds__(256, 1) ip_gemm_h_kernel() {
    const uint32_t sb = s2u(dynsm);
    const int tid = threadIdx.x;
    const int w = tid >> 5, t = tid & 31;
    const int r4 = t >> 2, q4 = t & 3;
    const int bn = blockIdx.x * 128, bm = blockIdx.y * 128, z = blockIdx.z;
    const __half* A = g_ipnorm_h;
    const __half* W = g_Wh + (size_t)z * DMOD * DIP;

    gemm_issue(sb, tid, bm, bn, A, W, 0, 0);
    gemm_issue(sb, tid, bm, bn, A, W, 1, 1);

    float oc[16][4] = {};
    const int rowselA = t & 15;
    const int winA = (t >> 4) << 4;                 // 0 or 16
    const int rowselB = (t & 7) + ((t & 16) >> 1);  // +8 if t>=16
    const int winB = (t & 8) << 1;                  // 0 or 16

    for (int ks = 0; ks < 20; ks++) {
        const int buf = ks & 1;
        if (ks < 18) asm volatile("cp.async.wait_group 1;");
        else         asm volatile("cp.async.wait_group 0;");
        __syncthreads();
        const uint32_t Ab = sb + buf * 18432;
        const uint32_t Bb = sb + 36864 + buf * 18432;
#pragma unroll
        for (int kb = 0; kb < 4; kb++) {
            uint32_t aa[4];
            ldsm4(aa, Ab + (w * 16 + rowselA) * 144 + kb * 32 + winA);
#pragma unroll
            for (int nbp = 0; nbp < 8; nbp++) {
                uint32_t bb[4];
                ldsm4(bb, Bb + (nbp * 16 + rowselB) * 144 + kb * 32 + winB);
                mma_f16(oc[2 * nbp],     aa, bb[0], bb[1]);
                mma_f16(oc[2 * nbp + 1], aa, bb[2], bb[3]);
            }
        }
        __syncthreads();
        if (ks + 2 < 20) gemm_issue(sb, tid, bm, bn, A, W, ks + 2, buf);
        else asm volatile("cp.async.commit_group;");
    }

    const int m_lo = bm + w * 16 + r4, m_hi = m_lo + 8;
#pragma unroll
    for (int nb = 0; nb < 16; nb++) {
        int n = bn + nb * 8 + q4 * 2;
        float2 vlo = { oc[nb][0], oc[nb][1] };
        float2 vhi = { oc[nb][2], oc[nb][3] };
        if (z == 0) {
            *(float2*)(g_ipk_raw + (size_t)m_lo * DMOD + n) = vlo;
            *(float2*)(g_ipk_raw + (size_t)m_hi * DMOD + n) = vhi;
        } else {
            int hh = n >> 7, dd = n & 127;
            *(float2*)(g_Vall + ((size_t)hh * LTOT + LIMG + m_lo) * HD + dd) = vlo;
            *(float2*)(g_Vall + ((size_t)hh * LTOT + LIMG + m_hi) * HD + dd) = vhi;
        }
    }
}

// ================= stage 4: RMS + fp16 pack ================
__device__ __forceinline__ float warp_sum(float s) {
#pragma unroll
    for (int off = 16; off; off >>= 1) s += __shfl_xor_sync(0xffffffffu, s, off);
    return s;
}
__device__ __forceinline__ void st_h4(__half* p, float a, float b, float c, float d) {
    uint2 u = { pkh(a, b), pkh(c, d) };
    *reinterpret_cast<uint2*>(p) = u;
}

__global__ void qkv_rms_kernel(const float* __restrict__ q,
                               const float* __restrict__ k,
                               const float* __restrict__ v,
                               const float* __restrict__ gq,
                               const float* __restrict__ gk) {
    int rid = blockIdx.x * 8 + (threadIdx.x >> 5);
    if (rid >= LIMG * H) return;
    int lane = threadIdx.x & 31;
    int l = rid / H, hh = rid % H;
    size_t src = (size_t)l * DMOD + hh * HD + lane * 4;

    float4 xv = *(const float4*)(q + src);
    float inv = rsqrtf(warp_sum(xv.x*xv.x + xv.y*xv.y + xv.z*xv.z + xv.w*xv.w) / 128.f + 1e-6f) * SCALE2;
    float4 gv = ((const float4*)gq)[lane];
    st_h4(g_Qh + ((size_t)hh * LIMG + l) * HD + lane * 4,
          xv.x*inv*gv.x, xv.y*inv*gv.y, xv.z*inv*gv.z, xv.w*inv*gv.w);

    xv = *(const float4*)(k + src);
    inv = rsqrtf(warp_sum(xv.x*xv.x + xv.y*xv.y + xv.z*xv.z + xv.w*xv.w) / 128.f + 1e-6f);
    gv = ((const float4*)gk)[lane];
    st_h4(g_Kh + ((size_t)hh * LTOT + l) * HD + lane * 4,
          xv.x*inv*gv.x, xv.y*inv*gv.y, xv.z*inv*gv.z, xv.w*inv*gv.w);

    *(float4*)(g_Vall + ((size_t)hh * LTOT + l) * HD + lane * 4) = *(const float4*)(v + src);
}

__global__ void ipk_rms_kernel(const float* __restrict__ gipk) {
    int rid = blockIdx.x * 8 + (threadIdx.x >> 5);
    if (rid >= LIP * H) return;
    int lane = threadIdx.x & 31;
    int l = rid / H, hh = rid % H;
    float4 xv = *(const float4*)(g_ipk_raw + (size_t)l * DMOD + hh * HD + lane * 4);
    float inv = rsqrtf(warp_sum(xv.x*xv.x + xv.y*xv.y + xv.z*xv.z + xv.w*xv.w) / 128.f + 1e-6f);
    float4 gv = ((const float4*)gipk)[lane];
    st_h4(g_Kh + ((size_t)hh * LTOT + LIMG + l) * HD + lane * 4,
          xv.x*inv*gv.x, xv.y*inv*gv.y, xv.z*inv*gv.z, xv.w*inv*gv.w);
}

// ================= stage 4b: V transpose to fp16 [h][d][key] ================
__global__ void vt_kernel() {
    float* sm = (float*)dynsm;                  // [128 keys][133]
    int t = blockIdx.x, hh = blockIdx.y, tid = threadIdx.x;
    const float4* vsrc = (const float4*)(g_Vall + ((size_t)hh * LTOT + (size_t)t * 128) * HD);
    for (int i = tid; i < 128 * 32; i += 256) {
        int kr = i >> 5, d4 = i & 31;
        float4 f = vsrc[kr * 32 + d4];
        sm[kr * 133 + d4 * 4 + 0] = f.x;
        sm[kr * 133 + d4 * 4 + 1] = f.y;
        sm[kr * 133 + d4 * 4 + 2] = f.z;
        sm[kr * 133 + d4 * 4 + 3] = f.w;
    }
    __syncthreads();
    for (int j = 0; j < 8; j++) {
        int g = tid + j * 256;
        int d = g >> 4, kc = g & 15;
        float f[8];
#pragma unroll
        for (int i = 0; i < 8; i++) f[i] = sm[(kc * 8 + i) * 133 + d];
        uint4 u = { pkh(f[0], f[1]), pkh(f[2], f[3]), pkh(f[4], f[5]), pkh(f[6], f[7]) };
        *reinterpret_cast<uint4*>(g_Vth + ((size_t)hh * HD + d) * LTOT + (size_t)t * 128 + kc * 8) = u;
    }
}

// ================= stage 5: mma.sync flash attention ========================
// SMEM: Q 128x272B | K 3 bufs of 64x272B | V 3 bufs of 128x144B
#define SQ_OFF  0
#define SK_OFF  34816
#define SK_BUF  17408
#define SV_OFF  (34816 + 3 * 17408)     // 87040
#define SV_BUF  18432
#define ATTN_SMEM (SV_OFF + 3 * SV_BUF) // 142336

__global__ void __launch_bounds__(256, 1) attn_kernel(float* __restrict__ out) {
    char* smem = dynsm;
    const uint32_t sb = s2u(smem);
    const int tid = threadIdx.x;
    const int w = tid >> 5, t = tid & 31;
    const int r4 = t >> 2, q4 = t & 3;
    const int hh = blockIdx.y, q0 = blockIdx.x * 128;

    // ldmatrix B-frag addressing (shared by K and V tiles)
    const int rowselB = (t & 7) + ((t & 16) >> 1);  // +8 for upper half-warp
    const int winB = (t & 8) << 1;                  // +16B for odd octet

    // ---- Q tile load (row stride 272B) ----
    const uint4* qg = (const uint4*)(g_Qh + ((size_t)hh * LIMG + q0) * HD);
    for (int i = tid; i < 2048; i += 256) {
        int rr = i >> 4, cc = i & 15;
        *(uint4*)(smem + SQ_OFF + rr * 272 + cc * 16) = qg[i];
    }

    // ---- issue first 3 K/V tiles via cp.async ----
    const __half* kgb = g_Kh + (size_t)hh * LTOT * HD;
    const __half* vgb = g_Vth + (size_t)hh * HD * LTOT;
#pragma unroll
    for (int pb = 0; pb < 3; pb++) {
        for (int n = 0; n < 4; n++) {
            int i = tid + n * 256;
            int kr = i >> 4, c = i & 15;
            cp16(sb + SK_OFF + pb * SK_BUF + kr * 272 + c * 16,
                 kgb + ((size_t)(pb * KT + kr)) * HD + c * 8);
            int d = i >> 3, c2 = i & 7;
            cp16(sb + SV_OFF + pb * SV_BUF + d * 144 + c2 * 16,
                 vgb + (size_t)d * LTOT + pb * KT + c2 * 8);
        }
        asm volatile("cp.async.commit_group;");
    }
    __syncthreads();   // Q visible

    // ---- Q fragments (held in registers) ----
    uint32_t qa[8][4];
#pragma unroll
    for (int kb = 0; kb < 8; kb++) {
        const char* base = smem + SQ_OFF + (w * 16 + r4) * 272 + (kb * 16 + 2 * q4) * 2;
        qa[kb][0] = *(const uint32_t*)(base);
        qa[kb][1] = *(const uint32_t*)(base + 8 * 272);
        qa[kb][2] = *(const uint32_t*)(base + 16);
        qa[kb][3] = *(const uint32_t*)(base + 8 * 272 + 16);
    }

    float m_lo = -1e30f, m_hi = -1e30f, l_lo = 0.f, l_hi = 0.f;
    float oc[16][4];
#pragma unroll
    for (int n = 0; n < 16; n++)
#pragma unroll
        for (int j = 0; j < 4; j++) oc[n][j] = 0.f;

    for (int it = 0; it < NIT; it++) {
        const int b = it % 3;
        if (it < NIT - 2)      asm volatile("cp.async.wait_group 2;");
        else if (it == NIT - 2) asm volatile("cp.async.wait_group 1;");
        else                    asm volatile("cp.async.wait_group 0;");
        __syncthreads();

        // ---- S = Q @ K^T (ldmatrix B-frags) ----
        float sc[8][4];
#pragma unroll
        for (int n = 0; n < 8; n++)
#pragma unroll
            for (int j = 0; j < 4; j++) sc[n][j] = 0.f;
        const uint32_t Kb = sb + SK_OFF + b * SK_BUF;
#pragma unroll
        for (int kb = 0; kb < 8; kb++) {
#pragma unroll
            for (int nbp = 0; nbp < 4; nbp++) {
                uint32_t bb[4];
                ldsm4(bb, Kb + (nbp * 16 + rowselB) * 272 + kb * 32 + winB);
                mma_f16(sc[2 * nbp],     qa[kb], bb[0], bb[1]);
                mma_f16(sc[2 * nbp + 1], qa[kb], bb[2], bb[3]);
            }
        }

        // ---- online softmax (base-2, ex2.approx) ----
        float mt_lo = -1e30f, mt_hi = -1e30f;
#pragma unroll
        for (int n = 0; n < 8; n++) {
            mt_lo = fmaxf(mt_lo, fmaxf(sc[n][0], sc[n][1]));
            mt_hi = fmaxf(mt_hi, fmaxf(sc[n][2], sc[n][3]));
        }
        mt_lo = fmaxf(mt_lo, __shfl_xor_sync(0xffffffffu, mt_lo, 1));
        mt_lo = fmaxf(mt_lo, __shfl_xor_sync(0xffffffffu, mt_lo, 2));
        mt_hi = fmaxf(mt_hi, __shfl_xor_sync(0xffffffffu, mt_hi, 1));
        mt_hi = fmaxf(mt_hi, __shfl_xor_sync(0xffffffffu, mt_hi, 2));
        float mn_lo = fmaxf(m_lo, mt_lo), mn_hi = fmaxf(m_hi, mt_hi);
        float co_lo = ex2(m_lo - mn_lo), co_hi = ex2(m_hi - mn_hi);
        float ps_lo = 0.f, ps_hi = 0.f;
#pragma unroll
        for (int n = 0; n < 8; n++) {
            sc[n][0] = ex2(sc[n][0] - mn_lo);
            sc[n][1] = ex2(sc[n][1] - mn_lo);
            sc[n][2] = ex2(sc[n][2] - mn_hi);
            sc[n][3] = ex2(sc[n][3] - mn_hi);
            ps_lo += sc[n][0] + sc[n][1];
            ps_hi += sc[n][2] + sc[n][3];
        }
        ps_lo += __shfl_xor_sync(0xffffffffu, ps_lo, 1);
        ps_lo += __shfl_xor_sync(0xffffffffu, ps_lo, 2);
        ps_hi += __shfl_xor_sync(0xffffffffu, ps_hi, 1);
        ps_hi += __shfl_xor_sync(0xffffffffu, ps_hi, 2);
        l_lo = l_lo * co_lo + ps_lo; m_lo = mn_lo;
        l_hi = l_hi * co_hi + ps_hi; m_hi = mn_hi;
#pragma unroll
        for (int n = 0; n < 16; n++) {
            oc[n][0] *= co_lo; oc[n][1] *= co_lo;
            oc[n][2] *= co_hi; oc[n][3] *= co_hi;
        }

        // ---- P fragments ----
        uint32_t pa[4][4];
#pragma unroll
        for (int kb = 0; kb < 4; kb++) {
            pa[kb][0] = pkh(sc[2*kb][0],   sc[2*kb][1]);
            pa[kb][1] = pkh(sc[2*kb][2],   sc[2*kb][3]);
            pa[kb][2] = pkh(sc[2*kb+1][0], sc[2*kb+1][1]);
            pa[kb][3] = pkh(sc[2*kb+1][2], sc[2*kb+1][3]);
        }

        // ---- O += P @ V (ldmatrix B-frags) ----
        const uint32_t Vb = sb + SV_OFF + b * SV_BUF;
#pragma unroll
        for (int kb = 0; kb < 4; kb++) {
#pragma unroll
            for (int nbp = 0; nbp < 8; nbp++) {
                uint32_t bb[4];
                ldsm4(bb, Vb + (nbp * 16 + rowselB) * 144 + kb * 32 + winB);
                mma_f16(oc[2 * nbp],     pa[kb], bb[0], bb[1]);
                mma_f16(oc[2 * nbp + 1], pa[kb], bb[2], bb[3]);
            }
        }
        __syncthreads();   // everyone done reading buf b

        // ---- refill buf b with tile it+3 ----
        if (it + 3 < NIT) {
            for (int n = 0; n < 4; n++) {
                int i = tid + n * 256;
                int kr = i >> 4, c = i & 15;
                cp16(sb + SK_OFF + b * SK_BUF + kr * 272 + c * 16,
                     kgb + ((size_t)((it + 3) * KT + kr)) * HD + c * 8);
                int d = i >> 3, c2 = i & 7;
                cp16(sb + SV_OFF + b * SV_BUF + d * 144 + c2 * 16,
                     vgb + (size_t)d * LTOT + (it + 3) * KT + c2 * 8);
            }
        }
        asm volatile("cp.async.commit_group;");
    }

    // ---- epilogue ----
    float il_lo = 1.f / l_lo, il_hi = 1.f / l_hi;
    float* orow_lo = out + (size_t)(q0 + w * 16 + r4) * DMOD + hh * HD + 2 * q4;
    float* orow_hi = orow_lo + (size_t)8 * DMOD;
#pragma unroll
    for (int nb = 0; nb < 16; nb++) {
        float2 vlo = { oc[nb][0] * il_lo, oc[nb][1] * il_lo };
        float2 vhi = { oc[nb][2] * il_hi, oc[nb][3] * il_hi };
        *(float2*)(orow_lo + nb * 8) = vlo;
        *(float2*)(orow_hi + nb * 8) = vhi;
    }
}

// ================= launch =====================================================
extern "C" void kernel_launch(void* const* d_in, const int* in_sizes, int n_in,
                              void* d_out, int out_size) {
    const float* ip   = (const float*)d_in[0];
    const float* q    = (const float*)d_in[1];
    const float* k    = (const float*)d_in[2];
    const float* v    = (const float*)d_in[3];
    const float* temb = (const float*)d_in[4];
    const float* wada = (const float*)d_in[5];
    const float* bada = (const float*)d_in[6];
    const float* wk   = (const float*)d_in[7];
    const float* wv   = (const float*)d_in[8];
    const float* gq   = (const float*)d_in[9];
    const float* gk   = (const float*)d_in[10];
    const float* gipk = (const float*)d_in[11];
    float* out = (float*)d_out;

    ada_kernel<<<(2 * DIP + 7) / 8, 256>>>(temb, wada, bada);
    adaln_kernel<<<LIP, 256>>>(ip);
    wconv_kernel<<<dim3(DMOD * DIP / 1024, 2), 256>>>(wk, wv);

    cudaFuncSetAttribute(ip_gemm_h_kernel, cudaFuncAttributeMaxDynamicSharedMemorySize, GEMM_SMEM);
    ip_gemm_h_kernel<<<dim3(DMOD / 128, LIP / 128, 2), 256, GEMM_SMEM>>>();

    qkv_rms_kernel<<<(LIMG * H + 7) / 8, 256>>>(q, k, v, gq, gk);
    ipk_rms_kernel<<<(LIP * H + 7) / 8, 256>>>(gipk);

    cudaFuncSetAttribute(vt_kernel, cudaFuncAttributeMaxDynamicSharedMemorySize, 128 * 133 * 4);
    vt_kernel<<<dim3(LTOT / 128, H), 256, 128 * 133 * 4>>>();

    cudaFuncSetAttribute(attn_kernel, cudaFuncAttributeMaxDynamicSharedMemorySize, ATTN_SMEM);
    attn_kernel<<<dim3(NQT, H), 256, ATTN_SMEM>>>(out);
}

// round 8
// speedup vs baseline: 14.0743x; 1.0382x over previous
#include <cuda_runtime.h>
#include <cuda_fp16.h>
#include <math.h>
#include <stdint.h>

#define H     24
#define LIMG  2048
#define LIP   512
#define DMOD  3072
#define DIP   1280
#define HD    128
#define LTOT  2560
#define KT    64
#define NIT   (LTOT / KT)       // 40
#define NQT   (LIMG / 128)      // 16
// 1/sqrt(128) * log2(e)  (exp2-based softmax)
#define SCALE2 0.1275174735772347f

// ================= scratch =================
__device__ float  g_e[2 * DIP];
__device__ __half g_ipnorm_h[LIP * DIP];
__device__ __half g_Wh[2 * (size_t)DMOD * DIP];
__device__ float  g_ipk_raw[LIP * DMOD];
__device__ float  g_Vall[(size_t)H * LTOT * HD];         // fp32 head-major V
__device__ __half g_Qh[(size_t)H * LIMG * HD];           // pre-scaled fp16 Q
__device__ __half g_Kh[(size_t)H * LTOT * HD];           // fp16 K (img+ip)
__device__ __half g_Vth[(size_t)H * HD * LTOT];          // fp16 V transposed [h][d][key]

__device__ __forceinline__ uint32_t s2u(const void* p) {
    uint32_t a;
    asm("{ .reg .u64 t; cvta.to.shared.u64 t, %1; cvt.u32.u64 %0, t; }" : "=r"(a) : "l"(p));
    return a;
}
__device__ __forceinline__ uint32_t pkh(float a, float b) {
    __half2 h = __floats2half2_rn(a, b);
    return *reinterpret_cast<uint32_t*>(&h);
}
__device__ __forceinline__ float ex2(float x) {
    float y;
    asm("ex2.approx.f32 %0, %1;" : "=f"(y) : "f"(x));
    return y;
}
__device__ __forceinline__ void mma_f16(float* c, const uint32_t* a, uint32_t b0, uint32_t b1) {
    asm volatile("mma.sync.aligned.m16n8k16.row.col.f32.f16.f16.f32 "
        "{%0,%1,%2,%3}, {%4,%5,%6,%7}, {%8,%9}, {%0,%1,%2,%3};"
        : "+f"(c[0]), "+f"(c[1]), "+f"(c[2]), "+f"(c[3])
        : "r"(a[0]), "r"(a[1]), "r"(a[2]), "r"(a[3]), "r"(b0), "r"(b1));
}
__device__ __forceinline__ void ldsm4(uint32_t* r, uint32_t addr) {
    asm volatile("ldmatrix.sync.aligned.m8n8.x4.shared.b16 {%0,%1,%2,%3}, [%4];"
        : "=r"(r[0]), "=r"(r[1]), "=r"(r[2]), "=r"(r[3]) : "r"(addr));
}
__device__ __forceinline__ void cp16(uint32_t dst, const void* src) {
    asm volatile("cp.async.cg.shared.global [%0], [%1], 16;" :: "r"(dst), "l"(src));
}

// single extern shared symbol for all dynamic-smem kernels
extern __shared__ __align__(16) char dynsm[];

// ================= stage 1: ada ================
__global__ void ada_kernel(const float* __restrict__ t_emb,
                           const float* __restrict__ w_ada,
                           const float* __restrict__ b_ada) {
    int o = blockIdx.x * 8 + (threadIdx.x >> 5);
    int lane = threadIdx.x & 31;
    if (o >= 2 * DIP) return;
    const float* w = w_ada + (size_t)o * DIP;
    float s = 0.f;
    for (int i = lane; i < DIP; i += 32) {
        float t = t_emb[i];
        s += (t / (1.f + expf(-t))) * w[i];
    }
#pragma unroll
    for (int off = 16; off; off >>= 1) s += __shfl_xor_sync(0xffffffffu, s, off);
    if (lane == 0) g_e[o] = s + b_ada[o];
}

// ================= stage 2: AdaLN -> fp16 ================
__global__ void adaln_kernel(const float* __restrict__ ip) {
    int row = blockIdx.x;
    const float* x = ip + (size_t)row * DIP;
    __shared__ float red1[8], red2[8];
    float s = 0.f, s2 = 0.f;
    for (int i = threadIdx.x; i < DIP; i += 256) {
        float v = x[i]; s += v; s2 += v * v;
    }
#pragma unroll
    for (int off = 16; off; off >>= 1) {
        s  += __shfl_xor_sync(0xffffffffu, s, off);
        s2 += __shfl_xor_sync(0xffffffffu, s2, off);
    }
    int w = threadIdx.x >> 5, lane = threadIdx.x & 31;
    if (lane == 0) { red1[w] = s; red2[w] = s2; }
    __syncthreads();
    float ts = 0.f, ts2 = 0.f;
#pragma unroll
    for (int i = 0; i < 8; i++) { ts += red1[i]; ts2 += red2[i]; }
    float mu = ts / DIP;
    float inv = rsqrtf(ts2 / DIP - mu * mu + 1e-6f);
    for (int i = threadIdx.x; i < DIP; i += 256) {
        float xn = (x[i] - mu) * inv;
        g_ipnorm_h[(size_t)row * DIP + i] = __float2half(xn * (1.f + g_e[DIP + i]) + g_e[i]);
    }
}

// ================= stage 2b: weight fp32 -> fp16 ================
__global__ void wconv_kernel(const float* __restrict__ wk, const float* __restrict__ wv) {
    size_t i = ((size_t)blockIdx.x * 256 + threadIdx.x) * 4;
    const float* src = blockIdx.y ? wv : wk;
    __half* dst = g_Wh + (size_t)blockIdx.y * DMOD * DIP;
    float4 f = *(const float4*)(src + i);
    uint2 u = { pkh(f.x, f.y), pkh(f.z, f.w) };
    *(uint2*)(dst + i) = u;
}

// ================= stage 3: fused ip GEMM (N = 6144) via mma.sync ============
// C[512 x 6144] = ipnorm_h[512 x 1280] @ [Wk;Wv][6144 x 1280]^T
// CTA tile 128x192 -> grid 4 x 32 = 128 CTAs (one wave). K-step 64, dbl-buffered.
// SMEM: A 2x(128x144B)=36864 | B 2x(192x144B)=55296  -> 92160 B
#define GEMM_SMEM 92160

__device__ __forceinline__ void gemm_issue(uint32_t sb, int tid, int bm, int bn,
                                           int ks, int buf) {
#pragma unroll
    for (int n = 0; n < 4; n++) {
        int i = tid + n * 256;
        int row = i >> 3, c = i & 7;
        cp16(sb + buf * 18432 + row * 144 + c * 16,
             g_ipnorm_h + (size_t)(bm + row) * DIP + ks * 64 + c * 8);
    }
#pragma unroll
    for (int n = 0; n < 6; n++) {
        int i = tid + n * 256;
        int row = i >> 3, c = i & 7;
        cp16(sb + 36864 + buf * 27648 + row * 144 + c * 16,
             g_Wh + (size_t)(bn + row) * DIP + ks * 64 + c * 8);
    }
    asm volatile("cp.async.commit_group;");
}

__global__ void __launch_bounds__(256, 1) ip_gemm_h_kernel() {
    const uint32_t sb = s2u(dynsm);
    const int tid = threadIdx.x;
    const int w = tid >> 5, t = tid & 31;
    const int r4 = t >> 2, q4 = t & 3;
    const int bn = blockIdx.x * 192, bm = blockIdx.y * 128;

    gemm_issue(sb, tid, bm, bn, 0, 0);
    gemm_issue(sb, tid, bm, bn, 1, 1);

    float oc[24][4] = {};
    const int rowselA = t & 15;
    const int winA = (t >> 4) << 4;                 // 0 or 16
    const int rowselB = (t & 7) + ((t & 16) >> 1);  // +8 if t>=16
    const int winB = (t & 8) << 1;                  // 0 or 16

    for (int ks = 0; ks < 20; ks++) {
        const int buf = ks & 1;
        if (ks < 18) asm volatile("cp.async.wait_group 1;");
        else         asm volatile("cp.async.wait_group 0;");
        __syncthreads();
        const uint32_t Ab = sb + buf * 18432;
        const uint32_t Bb = sb + 36864 + buf * 27648;
#pragma unroll
        for (int kb = 0; kb < 4; kb++) {
            uint32_t aa[4];
            ldsm4(aa, Ab + (w * 16 + rowselA) * 144 + kb * 32 + winA);
#pragma unroll
            for (int nbp = 0; nbp < 12; nbp++) {
                uint32_t bb[4];
                ldsm4(bb, Bb + (nbp * 16 + rowselB) * 144 + kb * 32 + winB);
                mma_f16(oc[2 * nbp],     aa, bb[0], bb[1]);
                mma_f16(oc[2 * nbp + 1], aa, bb[2], bb[3]);
            }
        }
        __syncthreads();
        if (ks + 2 < 20) gemm_issue(sb, tid, bm, bn, ks + 2, buf);
        else asm volatile("cp.async.commit_group;");
    }

    const int m_lo = bm + w * 16 + r4, m_hi = m_lo + 8;
#pragma unroll
    for (int nb = 0; nb < 24; nb++) {
        int n = bn + nb * 8 + q4 * 2;
        float2 vlo = { oc[nb][0], oc[nb][1] };
        float2 vhi = { oc[nb][2], oc[nb][3] };
        if (n < DMOD) {
            *(float2*)(g_ipk_raw + (size_t)m_lo * DMOD + n) = vlo;
            *(float2*)(g_ipk_raw + (size_t)m_hi * DMOD + n) = vhi;
        } else {
            int nn = n - DMOD;
            int hh = nn >> 7, dd = nn & 127;
            *(float2*)(g_Vall + ((size_t)hh * LTOT + LIMG + m_lo) * HD + dd) = vlo;
            *(float2*)(g_Vall + ((size_t)hh * LTOT + LIMG + m_hi) * HD + dd) = vhi;
        }
    }
}

// ================= stage 4: RMS + fp16 pack ================
__device__ __forceinline__ float warp_sum(float s) {
#pragma unroll
    for (int off = 16; off; off >>= 1) s += __shfl_xor_sync(0xffffffffu, s, off);
    return s;
}
__device__ __forceinline__ void st_h4(__half* p, float a, float b, float c, float d) {
    uint2 u = { pkh(a, b), pkh(c, d) };
    *reinterpret_cast<uint2*>(p) = u;
}

__global__ void qkv_rms_kernel(const float* __restrict__ q,
                               const float* __restrict__ k,
                               const float* __restrict__ v,
                               const float* __restrict__ gq,
                               const float* __restrict__ gk) {
    int rid = blockIdx.x * 8 + (threadIdx.x >> 5);
    if (rid >= LIMG * H) return;
    int lane = threadIdx.x & 31;
    int l = rid / H, hh = rid % H;
    size_t src = (size_t)l * DMOD + hh * HD + lane * 4;

    float4 xv = *(const float4*)(q + src);
    float inv = rsqrtf(warp_sum(xv.x*xv.x + xv.y*xv.y + xv.z*xv.z + xv.w*xv.w) / 128.f + 1e-6f) * SCALE2;
    float4 gv = ((const float4*)gq)[lane];
    st_h4(g_Qh + ((size_t)hh * LIMG + l) * HD + lane * 4,
          xv.x*inv*gv.x, xv.y*inv*gv.y, xv.z*inv*gv.z, xv.w*inv*gv.w);

    xv = *(const float4*)(k + src);
    inv = rsqrtf(warp_sum(xv.x*xv.x + xv.y*xv.y + xv.z*xv.z + xv.w*xv.w) / 128.f + 1e-6f);
    gv = ((const float4*)gk)[lane];
    st_h4(g_Kh + ((size_t)hh * LTOT + l) * HD + lane * 4,
          xv.x*inv*gv.x, xv.y*inv*gv.y, xv.z*inv*gv.z, xv.w*inv*gv.w);

    *(float4*)(g_Vall + ((size_t)hh * LTOT + l) * HD + lane * 4) = *(const float4*)(v + src);
}

__global__ void ipk_rms_kernel(const float* __restrict__ gipk) {
    int rid = blockIdx.x * 8 + (threadIdx.x >> 5);
    if (rid >= LIP * H) return;
    int lane = threadIdx.x & 31;
    int l = rid / H, hh = rid % H;
    float4 xv = *(const float4*)(g_ipk_raw + (size_t)l * DMOD + hh * HD + lane * 4);
    float inv = rsqrtf(warp_sum(xv.x*xv.x + xv.y*xv.y + xv.z*xv.z + xv.w*xv.w) / 128.f + 1e-6f);
    float4 gv = ((const float4*)gipk)[lane];
    st_h4(g_Kh + ((size_t)hh * LTOT + LIMG + l) * HD + lane * 4,
          xv.x*inv*gv.x, xv.y*inv*gv.y, xv.z*inv*gv.z, xv.w*inv*gv.w);
}

// ================= stage 4b: V transpose to fp16 [h][d][key] ================
__global__ void vt_kernel() {
    float* sm = (float*)dynsm;                  // [128 keys][133]
    int t = blockIdx.x, hh = blockIdx.y, tid = threadIdx.x;
    const float4* vsrc = (const float4*)(g_Vall + ((size_t)hh * LTOT + (size_t)t * 128) * HD);
    for (int i = tid; i < 128 * 32; i += 256) {
        int kr = i >> 5, d4 = i & 31;
        float4 f = vsrc[kr * 32 + d4];
        sm[kr * 133 + d4 * 4 + 0] = f.x;
        sm[kr * 133 + d4 * 4 + 1] = f.y;
        sm[kr * 133 + d4 * 4 + 2] = f.z;
        sm[kr * 133 + d4 * 4 + 3] = f.w;
    }
    __syncthreads();
    for (int j = 0; j < 8; j++) {
        int g = tid + j * 256;
        int d = g >> 4, kc = g & 15;
        float f[8];
#pragma unroll
        for (int i = 0; i < 8; i++) f[i] = sm[(kc * 8 + i) * 133 + d];
        uint4 u = { pkh(f[0], f[1]), pkh(f[2], f[3]), pkh(f[4], f[5]), pkh(f[6], f[7]) };
        *reinterpret_cast<uint4*>(g_Vth + ((size_t)hh * HD + d) * LTOT + (size_t)t * 128 + kc * 8) = u;
    }
}

// ================= stage 5: mma.sync flash attention (2 CTAs/SM) =============
// SMEM: Q 128x272B | K 2 bufs of 64x272B | V 2 bufs of 128x144B = 106496 B
#define SQ_OFF  0
#define SK_OFF  34816
#define SK_BUF  17408
#define SV_OFF  (34816 + 2 * 17408)     // 69632
#define SV_BUF  18432
#define ATTN_SMEM (SV_OFF + 2 * SV_BUF) // 106496

__global__ void __launch_bounds__(256, 2) attn_kernel(float* __restrict__ out) {
    char* smem = dynsm;
    const uint32_t sb = s2u(smem);
    const int tid = threadIdx.x;
    const int w = tid >> 5, t = tid & 31;
    const int r4 = t >> 2, q4 = t & 3;
    const int hh = blockIdx.y, q0 = blockIdx.x * 128;

    // ldmatrix addressing
    const int rowselA = t & 15;
    const int winA = (t >> 4) << 4;                 // 0 or 16
    const int rowselB = (t & 7) + ((t & 16) >> 1);  // +8 for upper half-warp
    const int winB = (t & 8) << 1;                  // +16B for odd octet

    // ---- Q tile load (row stride 272B) ----
    const uint4* qg = (const uint4*)(g_Qh + ((size_t)hh * LIMG + q0) * HD);
    for (int i = tid; i < 2048; i += 256) {
        int rr = i >> 4, cc = i & 15;
        *(uint4*)(smem + SQ_OFF + rr * 272 + cc * 16) = qg[i];
    }

    // ---- issue first 2 K/V tiles via cp.async ----
    const __half* kgb = g_Kh + (size_t)hh * LTOT * HD;
    const __half* vgb = g_Vth + (size_t)hh * HD * LTOT;
#pragma unroll
    for (int pb = 0; pb < 2; pb++) {
        for (int n = 0; n < 4; n++) {
            int i = tid + n * 256;
            int kr = i >> 4, c = i & 15;
            cp16(sb + SK_OFF + pb * SK_BUF + kr * 272 + c * 16,
                 kgb + ((size_t)(pb * KT + kr)) * HD + c * 8);
            int d = i >> 3, c2 = i & 7;
            cp16(sb + SV_OFF + pb * SV_BUF + d * 144 + c2 * 16,
                 vgb + (size_t)d * LTOT + pb * KT + c2 * 8);
        }
        asm volatile("cp.async.commit_group;");
    }
    __syncthreads();   // Q visible

    float m_lo = -1e30f, m_hi = -1e30f, l_lo = 0.f, l_hi = 0.f;
    float oc[16][4];
#pragma unroll
    for (int n = 0; n < 16; n++)
#pragma unroll
        for (int j = 0; j < 4; j++) oc[n][j] = 0.f;

    const uint32_t Qb = sb + SQ_OFF;

    for (int it = 0; it < NIT; it++) {
        const int b = it & 1;
        asm volatile("cp.async.wait_group 1;");
        __syncthreads();

        // ---- S = Q @ K^T (both operands via ldmatrix) ----
        float sc[8][4];
#pragma unroll
        for (int n = 0; n < 8; n++)
#pragma unroll
            for (int j = 0; j < 4; j++) sc[n][j] = 0.f;
        const uint32_t Kb = sb + SK_OFF + b * SK_BUF;
#pragma unroll
        for (int kb = 0; kb < 8; kb++) {
            uint32_t aa[4];
            ldsm4(aa, Qb + (w * 16 + rowselA) * 272 + kb * 32 + winA);
#pragma unroll
            for (int nbp = 0; nbp < 4; nbp++) {
                uint32_t bb[4];
                ldsm4(bb, Kb + (nbp * 16 + rowselB) * 272 + kb * 32 + winB);
                mma_f16(sc[2 * nbp],     aa, bb[0], bb[1]);
                mma_f16(sc[2 * nbp + 1], aa, bb[2], bb[3]);
            }
        }

        // ---- online softmax (base-2, ex2.approx) ----
        float mt_lo = -1e30f, mt_hi = -1e30f;
#pragma unroll
        for (int n = 0; n < 8; n++) {
            mt_lo = fmaxf(mt_lo, fmaxf(sc[n][0], sc[n][1]));
            mt_hi = fmaxf(mt_hi, fmaxf(sc[n][2], sc[n][3]));
        }
        mt_lo = fmaxf(mt_lo, __shfl_xor_sync(0xffffffffu, mt_lo, 1));
        mt_lo = fmaxf(mt_lo, __shfl_xor_sync(0xffffffffu, mt_lo, 2));
        mt_hi = fmaxf(mt_hi, __shfl_xor_sync(0xffffffffu, mt_hi, 1));
        mt_hi = fmaxf(mt_hi, __shfl_xor_sync(0xffffffffu, mt_hi, 2));
        float mn_lo = fmaxf(m_lo, mt_lo), mn_hi = fmaxf(m_hi, mt_hi);
        float co_lo = ex2(m_lo - mn_lo), co_hi = ex2(m_hi - mn_hi);
        float ps_lo = 0.f, ps_hi = 0.f;
#pragma unroll
        for (int n = 0; n < 8; n++) {
            sc[n][0] = ex2(sc[n][0] - mn_lo);
            sc[n][1] = ex2(sc[n][1] - mn_lo);
            sc[n][2] = ex2(sc[n][2] - mn_hi);
            sc[n][3] = ex2(sc[n][3] - mn_hi);
            ps_lo += sc[n][0] + sc[n][1];
            ps_hi += sc[n][2] + sc[n][3];
        }
        ps_lo += __shfl_xor_sync(0xffffffffu, ps_lo, 1);
        ps_lo += __shfl_xor_sync(0xffffffffu, ps_lo, 2);
        ps_hi += __shfl_xor_sync(0xffffffffu, ps_hi, 1);
        ps_hi += __shfl_xor_sync(0xffffffffu, ps_hi, 2);
        l_lo = l_lo * co_lo + ps_lo; m_lo = mn_lo;
        l_hi = l_hi * co_hi + ps_hi; m_hi = mn_hi;
#pragma unroll
        for (int n = 0; n < 16; n++) {
            oc[n][0] *= co_lo; oc[n][1] *= co_lo;
            oc[n][2] *= co_hi; oc[n][3] *= co_hi;
        }

        // ---- P fragments ----
        uint32_t pa[4][4];
#pragma unroll
        for (int kb = 0; kb < 4; kb++) {
            pa[kb][0] = pkh(sc[2*kb][0],   sc[2*kb][1]);
            pa[kb][1] = pkh(sc[2*kb][2],   sc[2*kb][3]);
            pa[kb][2] = pkh(sc[2*kb+1][0], sc[2*kb+1][1]);
            pa[kb][3] = pkh(sc[2*kb+1][2], sc[2*kb+1][3]);
        }

        // ---- O += P @ V (ldmatrix B-frags) ----
        const uint32_t Vb = sb + SV_OFF + b * SV_BUF;
#pragma unroll
        for (int kb = 0; kb < 4; kb++) {
#pragma unroll
            for (int nbp = 0; nbp < 8; nbp++) {
                uint32_t bb[4];
                ldsm4(bb, Vb + (nbp * 16 + rowselB) * 144 + kb * 32 + winB);
                mma_f16(oc[2 * nbp],     pa[kb], bb[0], bb[1]);
                mma_f16(oc[2 * nbp + 1], pa[kb], bb[2], bb[3]);
            }
        }
        __syncthreads();   // everyone done reading buf b

        // ---- refill buf b with tile it+2 (always commit to keep counts) ----
        if (it + 2 < NIT) {
            for (int n = 0; n < 4; n++) {
                int i = tid + n * 256;
                int kr = i >> 4, c = i & 15;
                cp16(sb + SK_OFF + b * SK_BUF + kr * 272 + c * 16,
                     kgb + ((size_t)((it + 2) * KT + kr)) * HD + c * 8);
                int d = i >> 3, c2 = i & 7;
                cp16(sb + SV_OFF + b * SV_BUF + d * 144 + c2 * 16,
                     vgb + (size_t)d * LTOT + (it + 2) * KT + c2 * 8);
            }
        }
        asm volatile("cp.async.commit_group;");
    }

    // ---- epilogue ----
    float il_lo = 1.f / l_lo, il_hi = 1.f / l_hi;
    float* orow_lo = out + (size_t)(q0 + w * 16 + r4) * DMOD + hh * HD + 2 * q4;
    float* orow_hi = orow_lo + (size_t)8 * DMOD;
#pragma unroll
    for (int nb = 0; nb < 16; nb++) {
        float2 vlo = { oc[nb][0] * il_lo, oc[nb][1] * il_lo };
        float2 vhi = { oc[nb][2] * il_hi, oc[nb][3] * il_hi };
        *(float2*)(orow_lo + nb * 8) = vlo;
        *(float2*)(orow_hi + nb * 8) = vhi;
    }
}

// ================= launch =====================================================
extern "C" void kernel_launch(void* const* d_in, const int* in_sizes, int n_in,
                              void* d_out, int out_size) {
    const float* ip   = (const float*)d_in[0];
    const float* q    = (const float*)d_in[1];
    const float* k    = (const float*)d_in[2];
    const float* v    = (const float*)d_in[3];
    const float* temb = (const float*)d_in[4];
    const float* wada = (const float*)d_in[5];
    const float* bada = (const float*)d_in[6];
    const float* wk   = (const float*)d_in[7];
    const float* wv   = (const float*)d_in[8];
    const float* gq   = (const float*)d_in[9];
    const float* gk   = (const float*)d_in[10];
    const float* gipk = (const float*)d_in[11];
    float* out = (float*)d_out;

    ada_kernel<<<(2 * DIP + 7) / 8, 256>>>(temb, wada, bada);
    adaln_kernel<<<LIP, 256>>>(ip);
    wconv_kernel<<<dim3(DMOD * DIP / 1024, 2), 256>>>(wk, wv);

    cudaFuncSetAttribute(ip_gemm_h_kernel, cudaFuncAttributeMaxDynamicSharedMemorySize, GEMM_SMEM);
    ip_gemm_h_kernel<<<dim3(DMOD * 2 / 192, LIP / 128), 256, GEMM_SMEM>>>();

    qkv_rms_kernel<<<(LIMG * H + 7) / 8, 256>>>(q, k, v, gq, gk);
    ipk_rms_kernel<<<(LIP * H + 7) / 8, 256>>>(gipk);

    cudaFuncSetAttribute(vt_kernel, cudaFuncAttributeMaxDynamicSharedMemorySize, 128 * 133 * 4);
    vt_kernel<<<dim3(LTOT / 128, H), 256, 128 * 133 * 4>>>();

    cudaFuncSetAttribute(attn_kernel, cudaFuncAttributeMaxDynamicSharedMemorySize, ATTN_SMEM);
    attn_kernel<<<dim3(NQT, H), 256, ATTN_SMEM>>>(out);
}

// round 9
// speedup vs baseline: 14.2073x; 1.0094x over previous
#include <cuda_runtime.h>
#include <cuda_fp16.h>
#include <math.h>
#include <stdint.h>

#define H     24
#define LIMG  2048
#define LIP   512
#define DMOD  3072
#define DIP   1280
#define HD    128
#define LTOT  2560
#define KT    64
#define NIT   (LTOT / KT)       // 40
#define NQT   (LIMG / 128)      // 16
// 1/sqrt(128) * log2(e)  (exp2-based softmax)
#define SCALE2 0.1275174735772347f
#define ONES2 0x3C003C00u       // half2(1.0, 1.0)

// ================= scratch =================
__device__ float  g_e[2 * DIP];
__device__ __half g_ipnorm_h[LIP * DIP];
__device__ __half g_Wh[2 * (size_t)DMOD * DIP];
__device__ float  g_ipk_raw[LIP * DMOD];
__device__ float  g_Vall[(size_t)H * LTOT * HD];         // fp32 head-major V
__device__ __half g_Qh[(size_t)H * LIMG * HD];           // pre-scaled fp16 Q
__device__ __half g_Kh[(size_t)H * LTOT * HD];           // fp16 K (img+ip)
__device__ __half g_Vth[(size_t)H * HD * LTOT];          // fp16 V transposed [h][d][key]

__device__ __forceinline__ uint32_t s2u(const void* p) {
    uint32_t a;
    asm("{ .reg .u64 t; cvta.to.shared.u64 t, %1; cvt.u32.u64 %0, t; }" : "=r"(a) : "l"(p));
    return a;
}
__device__ __forceinline__ uint32_t pkh(float a, float b) {
    __half2 h = __floats2half2_rn(a, b);
    return *reinterpret_cast<uint32_t*>(&h);
}
// pack two f32 into f16x2 (lo, hi)
__device__ __forceinline__ uint32_t pk2(float lo, float hi) {
    uint32_t d;
    asm("cvt.rn.f16x2.f32 %0, %1, %2;" : "=r"(d) : "f"(hi), "f"(lo));
    return d;
}
// packed half2 exp2
__device__ __forceinline__ uint32_t hex2(uint32_t x) {
    uint32_t d;
    asm("ex2.approx.f16x2 %0, %1;" : "=r"(d) : "r"(x));
    return d;
}
__device__ __forceinline__ float ex2(float x) {
    float y;
    asm("ex2.approx.f32 %0, %1;" : "=f"(y) : "f"(x));
    return y;
}
__device__ __forceinline__ void mma_f16(float* c, const uint32_t* a, uint32_t b0, uint32_t b1) {
    asm volatile("mma.sync.aligned.m16n8k16.row.col.f32.f16.f16.f32 "
        "{%0,%1,%2,%3}, {%4,%5,%6,%7}, {%8,%9}, {%0,%1,%2,%3};"
        : "+f"(c[0]), "+f"(c[1]), "+f"(c[2]), "+f"(c[3])
        : "r"(a[0]), "r"(a[1]), "r"(a[2]), "r"(a[3]), "r"(b0), "r"(b1));
}
__device__ __forceinline__ void ldsm4(uint32_t* r, uint32_t addr) {
    asm volatile("ldmatrix.sync.aligned.m8n8.x4.shared.b16 {%0,%1,%2,%3}, [%4];"
        : "=r"(r[0]), "=r"(r[1]), "=r"(r[2]), "=r"(r[3]) : "r"(addr));
}
__device__ __forceinline__ void cp16(uint32_t dst, const void* src) {
    asm volatile("cp.async.cg.shared.global [%0], [%1], 16;" :: "r"(dst), "l"(src));
}

// single extern shared symbol for all dynamic-smem kernels
extern __shared__ __align__(16) char dynsm[];

// ================= stage 1: ada ================
__global__ void ada_kernel(const float* __restrict__ t_emb,
                           const float* __restrict__ w_ada,
                           const float* __restrict__ b_ada) {
    int o = blockIdx.x * 8 + (threadIdx.x >> 5);
    int lane = threadIdx.x & 31;
    if (o >= 2 * DIP) return;
    const float* w = w_ada + (size_t)o * DIP;
    float s = 0.f;
    for (int i = lane; i < DIP; i += 32) {
        float t = t_emb[i];
        s += (t / (1.f + expf(-t))) * w[i];
    }
#pragma unroll
    for (int off = 16; off; off >>= 1) s += __shfl_xor_sync(0xffffffffu, s, off);
    if (lane == 0) g_e[o] = s + b_ada[o];
}

// ================= stage 2: AdaLN -> fp16 ================
__global__ void adaln_kernel(const float* __restrict__ ip) {
    int row = blockIdx.x;
    const float* x = ip + (size_t)row * DIP;
    __shared__ float red1[8], red2[8];
    float s = 0.f, s2 = 0.f;
    for (int i = threadIdx.x; i < DIP; i += 256) {
        float v = x[i]; s += v; s2 += v * v;
    }
#pragma unroll
    for (int off = 16; off; off >>= 1) {
        s  += __shfl_xor_sync(0xffffffffu, s, off);
        s2 += __shfl_xor_sync(0xffffffffu, s2, off);
    }
    int w = threadIdx.x >> 5, lane = threadIdx.x & 31;
    if (lane == 0) { red1[w] = s; red2[w] = s2; }
    __syncthreads();
    float ts = 0.f, ts2 = 0.f;
#pragma unroll
    for (int i = 0; i < 8; i++) { ts += red1[i]; ts2 += red2[i]; }
    float mu = ts / DIP;
    float inv = rsqrtf(ts2 / DIP - mu * mu + 1e-6f);
    for (int i = threadIdx.x; i < DIP; i += 256) {
        float xn = (x[i] - mu) * inv;
        g_ipnorm_h[(size_t)row * DIP + i] = __float2half(xn * (1.f + g_e[DIP + i]) + g_e[i]);
    }
}

// ================= stage 2b: weight fp32 -> fp16 ================
__global__ void wconv_kernel(const float* __restrict__ wk, const float* __restrict__ wv) {
    size_t i = ((size_t)blockIdx.x * 256 + threadIdx.x) * 4;
    const float* src = blockIdx.y ? wv : wk;
    __half* dst = g_Wh + (size_t)blockIdx.y * DMOD * DIP;
    float4 f = *(const float4*)(src + i);
    uint2 u = { pkh(f.x, f.y), pkh(f.z, f.w) };
    *(uint2*)(dst + i) = u;
}

// ================= stage 3: fused ip GEMM (N = 6144) via mma.sync ============
#define GEMM_SMEM 92160

__device__ __forceinline__ void gemm_issue(uint32_t sb, int tid, int bm, int bn,
                                           int ks, int buf) {
#pragma unroll
    for (int n = 0; n < 4; n++) {
        int i = tid + n * 256;
        int row = i >> 3, c = i & 7;
        cp16(sb + buf * 18432 + row * 144 + c * 16,
             g_ipnorm_h + (size_t)(bm + row) * DIP + ks * 64 + c * 8);
    }
#pragma unroll
    for (int n = 0; n < 6; n++) {
        int i = tid + n * 256;
        int row = i >> 3, c = i & 7;
        cp16(sb + 36864 + buf * 27648 + row * 144 + c * 16,
             g_Wh + (size_t)(bn + row) * DIP + ks * 64 + c * 8);
    }
    asm volatile("cp.async.commit_group;");
}

__global__ void __launch_bounds__(256, 1) ip_gemm_h_kernel() {
    const uint32_t sb = s2u(dynsm);
    const int tid = threadIdx.x;
    const int w = tid >> 5, t = tid & 31;
    const int r4 = t >> 2, q4 = t & 3;
    const int bn = blockIdx.x * 192, bm = blockIdx.y * 128;

    gemm_issue(sb, tid, bm, bn, 0, 0);
    gemm_issue(sb, tid, bm, bn, 1, 1);

    float oc[24][4] = {};
    const int rowselA = t & 15;
    const int winA = (t >> 4) << 4;
    const int rowselB = (t & 7) + ((t & 16) >> 1);
    const int winB = (t & 8) << 1;

    for (int ks = 0; ks < 20; ks++) {
        const int buf = ks & 1;
        if (ks < 18) asm volatile("cp.async.wait_group 1;");
        else         asm volatile("cp.async.wait_group 0;");
        __syncthreads();
        const uint32_t Ab = sb + buf * 18432;
        const uint32_t Bb = sb + 36864 + buf * 27648;
#pragma unroll
        for (int kb = 0; kb < 4; kb++) {
            uint32_t aa[4];
            ldsm4(aa, Ab + (w * 16 + rowselA) * 144 + kb * 32 + winA);
#pragma unroll
            for (int nbp = 0; nbp < 12; nbp++) {
                uint32_t bb[4];
                ldsm4(bb, Bb + (nbp * 16 + rowselB) * 144 + kb * 32 + winB);
                mma_f16(oc[2 * nbp],     aa, bb[0], bb[1]);
                mma_f16(oc[2 * nbp + 1], aa, bb[2], bb[3]);
            }
        }
        __syncthreads();
        if (ks + 2 < 20) gemm_issue(sb, tid, bm, bn, ks + 2, buf);
        else asm volatile("cp.async.commit_group;");
    }

    const int m_lo = bm + w * 16 + r4, m_hi = m_lo + 8;
#pragma unroll
    for (int nb = 0; nb < 24; nb++) {
        int n = bn + nb * 8 + q4 * 2;
        float2 vlo = { oc[nb][0], oc[nb][1] };
        float2 vhi = { oc[nb][2], oc[nb][3] };
        if (n < DMOD) {
            *(float2*)(g_ipk_raw + (size_t)m_lo * DMOD + n) = vlo;
            *(float2*)(g_ipk_raw + (size_t)m_hi * DMOD + n) = vhi;
        } else {
            int nn = n - DMOD;
            int hh = nn >> 7, dd = nn & 127;
            *(float2*)(g_Vall + ((size_t)hh * LTOT + LIMG + m_lo) * HD + dd) = vlo;
            *(float2*)(g_Vall + ((size_t)hh * LTOT + LIMG + m_hi) * HD + dd) = vhi;
        }
    }
}

// ================= stage 4: RMS + fp16 pack ================
__device__ __forceinline__ float warp_sum(float s) {
#pragma unroll
    for (int off = 16; off; off >>= 1) s += __shfl_xor_sync(0xffffffffu, s, off);
    return s;
}
__device__ __forceinline__ void st_h4(__half* p, float a, float b, float c, float d) {
    uint2 u = { pkh(a, b), pkh(c, d) };
    *reinterpret_cast<uint2*>(p) = u;
}

__global__ void qkv_rms_kernel(const float* __restrict__ q,
                               const float* __restrict__ k,
                               const float* __restrict__ v,
                               const float* __restrict__ gq,
                               const float* __restrict__ gk) {
    int rid = blockIdx.x * 8 + (threadIdx.x >> 5);
    if (rid >= LIMG * H) return;
    int lane = threadIdx.x & 31;
    int l = rid / H, hh = rid % H;
    size_t src = (size_t)l * DMOD + hh * HD + lane * 4;

    float4 xv = *(const float4*)(q + src);
    float inv = rsqrtf(warp_sum(xv.x*xv.x + xv.y*xv.y + xv.z*xv.z + xv.w*xv.w) / 128.f + 1e-6f) * SCALE2;
    float4 gv = ((const float4*)gq)[lane];
    st_h4(g_Qh + ((size_t)hh * LIMG + l) * HD + lane * 4,
          xv.x*inv*gv.x, xv.y*inv*gv.y, xv.z*inv*gv.z, xv.w*inv*gv.w);

    xv = *(const float4*)(k + src);
    inv = rsqrtf(warp_sum(xv.x*xv.x + xv.y*xv.y + xv.z*xv.z + xv.w*xv.w) / 128.f + 1e-6f);
    gv = ((const float4*)gk)[lane];
    st_h4(g_Kh + ((size_t)hh * LTOT + l) * HD + lane * 4,
          xv.x*inv*gv.x, xv.y*inv*gv.y, xv.z*inv*gv.z, xv.w*inv*gv.w);

    *(float4*)(g_Vall + ((size_t)hh * LTOT + l) * HD + lane * 4) = *(const float4*)(v + src);
}

__global__ void ipk_rms_kernel(const float* __restrict__ gipk) {
    int rid = blockIdx.x * 8 + (threadIdx.x >> 5);
    if (rid >= LIP * H) return;
    int lane = threadIdx.x & 31;
    int l = rid / H, hh = rid % H;
    float4 xv = *(const float4*)(g_ipk_raw + (size_t)l * DMOD + hh * HD + lane * 4);
    float inv = rsqrtf(warp_sum(xv.x*xv.x + xv.y*xv.y + xv.z*xv.z + xv.w*xv.w) / 128.f + 1e-6f);
    float4 gv = ((const float4*)gipk)[lane];
    st_h4(g_Kh + ((size_t)hh * LTOT + LIMG + l) * HD + lane * 4,
          xv.x*inv*gv.x, xv.y*inv*gv.y, xv.z*inv*gv.z, xv.w*inv*gv.w);
}

// ================= stage 4b: V transpose to fp16 [h][d][key] ================
__global__ void vt_kernel() {
    float* sm = (float*)dynsm;                  // [128 keys][133]
    int t = blockIdx.x, hh = blockIdx.y, tid = threadIdx.x;
    const float4* vsrc = (const float4*)(g_Vall + ((size_t)hh * LTOT + (size_t)t * 128) * HD);
    for (int i = tid; i < 128 * 32; i += 256) {
        int kr = i >> 5, d4 = i & 31;
        float4 f = vsrc[kr * 32 + d4];
        sm[kr * 133 + d4 * 4 + 0] = f.x;
        sm[kr * 133 + d4 * 4 + 1] = f.y;
        sm[kr * 133 + d4 * 4 + 2] = f.z;
        sm[kr * 133 + d4 * 4 + 3] = f.w;
    }
    __syncthreads();
    for (int j = 0; j < 8; j++) {
        int g = tid + j * 256;
        int d = g >> 4, kc = g & 15;
        float f[8];
#pragma unroll
        for (int i = 0; i < 8; i++) f[i] = sm[(kc * 8 + i) * 133 + d];
        uint4 u = { pkh(f[0], f[1]), pkh(f[2], f[3]), pkh(f[4], f[5]), pkh(f[6], f[7]) };
        *reinterpret_cast<uint4*>(g_Vth + ((size_t)hh * HD + d) * LTOT + (size_t)t * 128 + kc * 8) = u;
    }
}

// ================= stage 5: mma.sync flash attention ========================
// SMEM: Q 128x272B | K 2 bufs of 64x272B | V 2 bufs of 128x144B = 106496 B
#define SQ_OFF  0
#define SK_OFF  34816
#define SK_BUF  17408
#define SV_OFF  (34816 + 2 * 17408)     // 69632
#define SV_BUF  18432
#define ATTN_SMEM (SV_OFF + 2 * SV_BUF) // 106496

__global__ void __launch_bounds__(256, 1) attn_kernel(float* __restrict__ out) {
    char* smem = dynsm;
    const uint32_t sb = s2u(smem);
    const int tid = threadIdx.x;
    const int w = tid >> 5, t = tid & 31;
    const int r4 = t >> 2, q4 = t & 3;
    const int hh = blockIdx.y, q0 = blockIdx.x * 128;

    const int rowselA = t & 15;
    const int winA = (t >> 4) << 4;
    const int rowselB = (t & 7) + ((t & 16) >> 1);
    const int winB = (t & 8) << 1;

    // ---- Q tile load (row stride 272B) ----
    const uint4* qg = (const uint4*)(g_Qh + ((size_t)hh * LIMG + q0) * HD);
    for (int i = tid; i < 2048; i += 256) {
        int rr = i >> 4, cc = i & 15;
        *(uint4*)(smem + SQ_OFF + rr * 272 + cc * 16) = qg[i];
    }

    // ---- issue first 2 K/V tiles via cp.async ----
    const __half* kgb = g_Kh + (size_t)hh * LTOT * HD;
    const __half* vgb = g_Vth + (size_t)hh * HD * LTOT;
#pragma unroll
    for (int pb = 0; pb < 2; pb++) {
        for (int n = 0; n < 4; n++) {
            int i = tid + n * 256;
            int kr = i >> 4, c = i & 15;
            cp16(sb + SK_OFF + pb * SK_BUF + kr * 272 + c * 16,
                 kgb + ((size_t)(pb * KT + kr)) * HD + c * 8);
            int d = i >> 3, c2 = i & 7;
            cp16(sb + SV_OFF + pb * SV_BUF + d * 144 + c2 * 16,
                 vgb + (size_t)d * LTOT + pb * KT + c2 * 8);
        }
        asm volatile("cp.async.commit_group;");
    }
    __syncthreads();   // Q visible

    // ---- pinned Q fragments ----
    uint32_t qa[8][4];
#pragma unroll
    for (int kb = 0; kb < 8; kb++)
        ldsm4(qa[kb], sb + SQ_OFF + (w * 16 + rowselA) * 272 + kb * 32 + winA);

    float m_lo = -1e30f, m_hi = -1e30f;
    float oc[16][4];
#pragma unroll
    for (int n = 0; n < 16; n++)
#pragma unroll
        for (int j = 0; j < 4; j++) oc[n][j] = 0.f;
    float lacc[4] = {0.f, 0.f, 0.f, 0.f};     // row-sum accumulator (ones-MMA)

    for (int it = 0; it < NIT; it++) {
        const int b = it & 1;
        asm volatile("cp.async.wait_group 1;");
        __syncthreads();

        // ---- S = Q @ K^T ----
        float sc[8][4];
#pragma unroll
        for (int n = 0; n < 8; n++)
#pragma unroll
            for (int j = 0; j < 4; j++) sc[n][j] = 0.f;
        const uint32_t Kb = sb + SK_OFF + b * SK_BUF;
#pragma unroll
        for (int kb = 0; kb < 8; kb++) {
#pragma unroll
            for (int nbp = 0; nbp < 4; nbp++) {
                uint32_t bb[4];
                ldsm4(bb, Kb + (nbp * 16 + rowselB) * 272 + kb * 32 + winB);
                mma_f16(sc[2 * nbp],     qa[kb], bb[0], bb[1]);
                mma_f16(sc[2 * nbp + 1], qa[kb], bb[2], bb[3]);
            }
        }

        // ---- running max ----
        float mt_lo = -1e30f, mt_hi = -1e30f;
#pragma unroll
        for (int n = 0; n < 8; n++) {
            mt_lo = fmaxf(mt_lo, fmaxf(sc[n][0], sc[n][1]));
            mt_hi = fmaxf(mt_hi, fmaxf(sc[n][2], sc[n][3]));
        }
        mt_lo = fmaxf(mt_lo, __shfl_xor_sync(0xffffffffu, mt_lo, 1));
        mt_lo = fmaxf(mt_lo, __shfl_xor_sync(0xffffffffu, mt_lo, 2));
        mt_hi = fmaxf(mt_hi, __shfl_xor_sync(0xffffffffu, mt_hi, 1));
        mt_hi = fmaxf(mt_hi, __shfl_xor_sync(0xffffffffu, mt_hi, 2));
        float mn_lo = fmaxf(m_lo, mt_lo), mn_hi = fmaxf(m_hi, mt_hi);

        // ---- rescale only if max moved anywhere in the warp ----
        bool upd = (mn_lo > m_lo) | (mn_hi > m_hi);
        if (__any_sync(0xffffffffu, upd)) {
            float co_lo = ex2(m_lo - mn_lo), co_hi = ex2(m_hi - mn_hi);
#pragma unroll
            for (int n = 0; n < 16; n++) {
                oc[n][0] *= co_lo; oc[n][1] *= co_lo;
                oc[n][2] *= co_hi; oc[n][3] *= co_hi;
            }
            lacc[0] *= co_lo; lacc[1] *= co_lo;
            lacc[2] *= co_hi; lacc[3] *= co_hi;
        }
        m_lo = mn_lo; m_hi = mn_hi;

        // ---- P fragments: packed f16x2 exp2 ----
        uint32_t pa[4][4];
#pragma unroll
        for (int kb = 0; kb < 4; kb++) {
            pa[kb][0] = hex2(pk2(sc[2*kb][0]   - mn_lo, sc[2*kb][1]   - mn_lo));
            pa[kb][1] = hex2(pk2(sc[2*kb][2]   - mn_hi, sc[2*kb][3]   - mn_hi));
            pa[kb][2] = hex2(pk2(sc[2*kb+1][0] - mn_lo, sc[2*kb+1][1] - mn_lo));
            pa[kb][3] = hex2(pk2(sc[2*kb+1][2] - mn_hi, sc[2*kb+1][3] - mn_hi));
        }

        // ---- l += P @ ones (row sums, no shuffles) ----
#pragma unroll
        for (int kb = 0; kb < 4; kb++)
            mma_f16(lacc, pa[kb], ONES2, ONES2);

        // ---- O += P @ V ----
        const uint32_t Vb = sb + SV_OFF + b * SV_BUF;
#pragma unroll
        for (int kb = 0; kb < 4; kb++) {
#pragma unroll
            for (int nbp = 0; nbp < 8; nbp++) {
                uint32_t bb[4];
                ldsm4(bb, Vb + (nbp * 16 + rowselB) * 144 + kb * 32 + winB);
                mma_f16(oc[2 * nbp],     pa[kb], bb[0], bb[1]);
                mma_f16(oc[2 * nbp + 1], pa[kb], bb[2], bb[3]);
            }
        }
        __syncthreads();   // everyone done reading buf b

        // ---- refill buf b with tile it+2 (always commit to keep counts) ----
        if (it + 2 < NIT) {
            for (int n = 0; n < 4; n++) {
                int i = tid + n * 256;
                int kr = i >> 4, c = i & 15;
                cp16(sb + SK_OFF + b * SK_BUF + kr * 272 + c * 16,
                     kgb + ((size_t)((it + 2) * KT + kr)) * HD + c * 8);
                int d = i >> 3, c2 = i & 7;
                cp16(sb + SV_OFF + b * SV_BUF + d * 144 + c2 * 16,
                     vgb + (size_t)d * LTOT + (it + 2) * KT + c2 * 8);
            }
        }
        asm volatile("cp.async.commit_group;");
    }

    // ---- epilogue ----
    float il_lo = 1.f / lacc[0], il_hi = 1.f / lacc[2];
    float* orow_lo = out + (size_t)(q0 + w * 16 + r4) * DMOD + hh * HD + 2 * q4;
    float* orow_hi = orow_lo + (size_t)8 * DMOD;
#pragma unroll
    for (int nb = 0; nb < 16; nb++) {
        float2 vlo = { oc[nb][0] * il_lo, oc[nb][1] * il_lo };
        float2 vhi = { oc[nb][2] * il_hi, oc[nb][3] * il_hi };
        *(float2*)(orow_lo + nb * 8) = vlo;
        *(float2*)(orow_hi + nb * 8) = vhi;
    }
}

// ================= launch =====================================================
extern "C" void kernel_launch(void* const* d_in, const int* in_sizes, int n_in,
                              void* d_out, int out_size) {
    const float* ip   = (const float*)d_in[0];
    const float* q    = (const float*)d_in[1];
    const float* k    = (const float*)d_in[2];
    const float* v    = (const float*)d_in[3];
    const float* temb = (const float*)d_in[4];
    const float* wada = (const float*)d_in[5];
    const float* bada = (const float*)d_in[6];
    const float* wk   = (const float*)d_in[7];
    const float* wv   = (const float*)d_in[8];
    const float* gq   = (const float*)d_in[9];
    const float* gk   = (const float*)d_in[10];
    const float* gipk = (const float*)d_in[11];
    float* out = (float*)d_out;

    ada_kernel<<<(2 * DIP + 7) / 8, 256>>>(temb, wada, bada);
    adaln_kernel<<<LIP, 256>>>(ip);
    wconv_kernel<<<dim3(DMOD * DIP / 1024, 2), 256>>>(wk, wv);

    cudaFuncSetAttribute(ip_gemm_h_kernel, cudaFuncAttributeMaxDynamicSharedMemorySize, GEMM_SMEM);
    ip_gemm_h_kernel<<<dim3(DMOD * 2 / 192, LIP / 128), 256, GEMM_SMEM>>>();

    qkv_rms_kernel<<<(LIMG * H + 7) / 8, 256>>>(q, k, v, gq, gk);
    ipk_rms_kernel<<<(LIP * H + 7) / 8, 256>>>(gipk);

    cudaFuncSetAttribute(vt_kernel, cudaFuncAttributeMaxDynamicSharedMemorySize, 128 * 133 * 4);
    vt_kernel<<<dim3(LTOT / 128, H), 256, 128 * 133 * 4>>>();

    cudaFuncSetAttribute(attn_kernel, cudaFuncAttributeMaxDynamicSharedMemorySize, ATTN_SMEM);
    attn_kernel<<<dim3(NQT, H), 256, ATTN_SMEM>>>(out);
}

// round 10
// speedup vs baseline: 14.3083x; 1.0071x over previous
#include <cuda_runtime.h>
#include <cuda_fp16.h>
#include <math.h>
#include <stdint.h>

#define H     24
#define LIMG  2048
#define LIP   512
#define DMOD  3072
#define DIP   1280
#define HD    128
#define LTOT  2560
#define KT    64
#define NIT   (LTOT / KT)       // 40
// 1/sqrt(128) * log2(e)  (exp2-based softmax)
#define SCALE2 0.1275174735772347f
#define ONES2 0x3C003C00u       // half2(1.0, 1.0)

// ================= scratch =================
__device__ float  g_e[2 * DIP];
__device__ __half g_ipnorm_h[LIP * DIP];
__device__ __half g_Wh[2 * (size_t)DMOD * DIP];
__device__ float  g_ipk_raw[LIP * DMOD];
__device__ float  g_Vall[(size_t)H * LTOT * HD];         // fp32 head-major V
__device__ __half g_Qh[(size_t)H * LIMG * HD];           // pre-scaled fp16 Q
__device__ __half g_Kh[(size_t)H * LTOT * HD];           // fp16 K (img+ip)
__device__ __half g_Vth[(size_t)H * HD * LTOT];          // fp16 V transposed [h][d][key]

__device__ __forceinline__ uint32_t s2u(const void* p) {
    uint32_t a;
    asm("{ .reg .u64 t; cvta.to.shared.u64 t, %1; cvt.u32.u64 %0, t; }" : "=r"(a) : "l"(p));
    return a;
}
__device__ __forceinline__ uint32_t pkh(float a, float b) {
    __half2 h = __floats2half2_rn(a, b);
    return *reinterpret_cast<uint32_t*>(&h);
}
__device__ __forceinline__ uint32_t pk2(float lo, float hi) {
    uint32_t d;
    asm("cvt.rn.f16x2.f32 %0, %1, %2;" : "=r"(d) : "f"(hi), "f"(lo));
    return d;
}
__device__ __forceinline__ uint32_t hex2(uint32_t x) {
    uint32_t d;
    asm("ex2.approx.f16x2 %0, %1;" : "=r"(d) : "r"(x));
    return d;
}
__device__ __forceinline__ float ex2(float x) {
    float y;
    asm("ex2.approx.f32 %0, %1;" : "=f"(y) : "f"(x));
    return y;
}
__device__ __forceinline__ void mma_f16(float* c, const uint32_t* a, uint32_t b0, uint32_t b1) {
    asm volatile("mma.sync.aligned.m16n8k16.row.col.f32.f16.f16.f32 "
        "{%0,%1,%2,%3}, {%4,%5,%6,%7}, {%8,%9}, {%0,%1,%2,%3};"
        : "+f"(c[0]), "+f"(c[1]), "+f"(c[2]), "+f"(c[3])
        : "r"(a[0]), "r"(a[1]), "r"(a[2]), "r"(a[3]), "r"(b0), "r"(b1));
}
__device__ __forceinline__ void ldsm4(uint32_t* r, uint32_t addr) {
    asm volatile("ldmatrix.sync.aligned.m8n8.x4.shared.b16 {%0,%1,%2,%3}, [%4];"
        : "=r"(r[0]), "=r"(r[1]), "=r"(r[2]), "=r"(r[3]) : "r"(addr));
}
__device__ __forceinline__ void cp16(uint32_t dst, const void* src) {
    asm volatile("cp.async.cg.shared.global [%0], [%1], 16;" :: "r"(dst), "l"(src));
}

// single extern shared symbol for all dynamic-smem kernels
extern __shared__ __align__(16) char dynsm[];

// ================= stage 1: ada ================
__global__ void ada_kernel(const float* __restrict__ t_emb,
                           const float* __restrict__ w_ada,
                           const float* __restrict__ b_ada) {
    int o = blockIdx.x * 8 + (threadIdx.x >> 5);
    int lane = threadIdx.x & 31;
    if (o >= 2 * DIP) return;
    const float* w = w_ada + (size_t)o * DIP;
    float s = 0.f;
    for (int i = lane; i < DIP; i += 32) {
        float t = t_emb[i];
        s += (t / (1.f + expf(-t))) * w[i];
    }
#pragma unroll
    for (int off = 16; off; off >>= 1) s += __shfl_xor_sync(0xffffffffu, s, off);
    if (lane == 0) g_e[o] = s + b_ada[o];
}

// ================= stage 2: AdaLN -> fp16 ================
__global__ void adaln_kernel(const float* __restrict__ ip) {
    int row = blockIdx.x;
    const float* x = ip + (size_t)row * DIP;
    __shared__ float red1[8], red2[8];
    float s = 0.f, s2 = 0.f;
    for (int i = threadIdx.x; i < DIP; i += 256) {
        float v = x[i]; s += v; s2 += v * v;
    }
#pragma unroll
    for (int off = 16; off; off >>= 1) {
        s  += __shfl_xor_sync(0xffffffffu, s, off);
        s2 += __shfl_xor_sync(0xffffffffu, s2, off);
    }
    int w = threadIdx.x >> 5, lane = threadIdx.x & 31;
    if (lane == 0) { red1[w] = s; red2[w] = s2; }
    __syncthreads();
    float ts = 0.f, ts2 = 0.f;
#pragma unroll
    for (int i = 0; i < 8; i++) { ts += red1[i]; ts2 += red2[i]; }
    float mu = ts / DIP;
    float inv = rsqrtf(ts2 / DIP - mu * mu + 1e-6f);
    for (int i = threadIdx.x; i < DIP; i += 256) {
        float xn = (x[i] - mu) * inv;
        g_ipnorm_h[(size_t)row * DIP + i] = __float2half(xn * (1.f + g_e[DIP + i]) + g_e[i]);
    }
}

// ================= stage 2b: weight fp32 -> fp16 ================
__global__ void wconv_kernel(const float* __restrict__ wk, const float* __restrict__ wv) {
    size_t i = ((size_t)blockIdx.x * 256 + threadIdx.x) * 4;
    const float* src = blockIdx.y ? wv : wk;
    __half* dst = g_Wh + (size_t)blockIdx.y * DMOD * DIP;
    float4 f = *(const float4*)(src + i);
    uint2 u = { pkh(f.x, f.y), pkh(f.z, f.w) };
    *(uint2*)(dst + i) = u;
}

// ================= stage 3: fused ip GEMM (N = 6144) via mma.sync ============
#define GEMM_SMEM 92160

__device__ __forceinline__ void gemm_issue(uint32_t sb, int tid, int bm, int bn,
                                           int ks, int buf) {
#pragma unroll
    for (int n = 0; n < 4; n++) {
        int i = tid + n * 256;
        int row = i >> 3, c = i & 7;
        cp16(sb + buf * 18432 + row * 144 + c * 16,
             g_ipnorm_h + (size_t)(bm + row) * DIP + ks * 64 + c * 8);
    }
#pragma unroll
    for (int n = 0; n < 6; n++) {
        int i = tid + n * 256;
        int row = i >> 3, c = i & 7;
        cp16(sb + 36864 + buf * 27648 + row * 144 + c * 16,
             g_Wh + (size_t)(bn + row) * DIP + ks * 64 + c * 8);
    }
    asm volatile("cp.async.commit_group;");
}

__global__ void __launch_bounds__(256, 1) ip_gemm_h_kernel() {
    const uint32_t sb = s2u(dynsm);
    const int tid = threadIdx.x;
    const int w = tid >> 5, t = tid & 31;
    const int r4 = t >> 2, q4 = t & 3;
    const int bn = blockIdx.x * 192, bm = blockIdx.y * 128;

    gemm_issue(sb, tid, bm, bn, 0, 0);
    gemm_issue(sb, tid, bm, bn, 1, 1);

    float oc[24][4] = {};
    const int rowselA = t & 15;
    const int winA = (t >> 4) << 4;
    const int rowselB = (t & 7) + ((t & 16) >> 1);
    const int winB = (t & 8) << 1;

    for (int ks = 0; ks < 20; ks++) {
        const int buf = ks & 1;
        if (ks < 18) asm volatile("cp.async.wait_group 1;");
        else         asm volatile("cp.async.wait_group 0;");
        __syncthreads();
        const uint32_t Ab = sb + buf * 18432;
        const uint32_t Bb = sb + 36864 + buf * 27648;
#pragma unroll
        for (int kb = 0; kb < 4; kb++) {
            uint32_t aa[4];
            ldsm4(aa, Ab + (w * 16 + rowselA) * 144 + kb * 32 + winA);
#pragma unroll
            for (int nbp = 0; nbp < 12; nbp++) {
                uint32_t bb[4];
                ldsm4(bb, Bb + (nbp * 16 + rowselB) * 144 + kb * 32 + winB);
                mma_f16(oc[2 * nbp],     aa, bb[0], bb[1]);
                mma_f16(oc[2 * nbp + 1], aa, bb[2], bb[3]);
            }
        }
        __syncthreads();
        if (ks + 2 < 20) gemm_issue(sb, tid, bm, bn, ks + 2, buf);
        else asm volatile("cp.async.commit_group;");
    }

    const int m_lo = bm + w * 16 + r4, m_hi = m_lo + 8;
#pragma unroll
    for (int nb = 0; nb < 24; nb++) {
        int n = bn + nb * 8 + q4 * 2;
        float2 vlo = { oc[nb][0], oc[nb][1] };
        float2 vhi = { oc[nb][2], oc[nb][3] };
        if (n < DMOD) {
            *(float2*)(g_ipk_raw + (size_t)m_lo * DMOD + n) = vlo;
            *(float2*)(g_ipk_raw + (size_t)m_hi * DMOD + n) = vhi;
        } else {
            int nn = n - DMOD;
            int hh = nn >> 7, dd = nn & 127;
            *(float2*)(g_Vall + ((size_t)hh * LTOT + LIMG + m_lo) * HD + dd) = vlo;
            *(float2*)(g_Vall + ((size_t)hh * LTOT + LIMG + m_hi) * HD + dd) = vhi;
        }
    }
}

// ================= stage 4: RMS + fp16 pack ================
__device__ __forceinline__ float warp_sum(float s) {
#pragma unroll
    for (int off = 16; off; off >>= 1) s += __shfl_xor_sync(0xffffffffu, s, off);
    return s;
}
__device__ __forceinline__ void st_h4(__half* p, float a, float b, float c, float d) {
    uint2 u = { pkh(a, b), pkh(c, d) };
    *reinterpret_cast<uint2*>(p) = u;
}

__global__ void qkv_rms_kernel(const float* __restrict__ q,
                               const float* __restrict__ k,
                               const float* __restrict__ v,
                               const float* __restrict__ gq,
                               const float* __restrict__ gk) {
    int rid = blockIdx.x * 8 + (threadIdx.x >> 5);
    if (rid >= LIMG * H) return;
    int lane = threadIdx.x & 31;
    int l = rid / H, hh = rid % H;
    size_t src = (size_t)l * DMOD + hh * HD + lane * 4;

    float4 xv = *(const float4*)(q + src);
    float inv = rsqrtf(warp_sum(xv.x*xv.x + xv.y*xv.y + xv.z*xv.z + xv.w*xv.w) / 128.f + 1e-6f) * SCALE2;
    float4 gv = ((const float4*)gq)[lane];
    st_h4(g_Qh + ((size_t)hh * LIMG + l) * HD + lane * 4,
          xv.x*inv*gv.x, xv.y*inv*gv.y, xv.z*inv*gv.z, xv.w*inv*gv.w);

    xv = *(const float4*)(k + src);
    inv = rsqrtf(warp_sum(xv.x*xv.x + xv.y*xv.y + xv.z*xv.z + xv.w*xv.w) / 128.f + 1e-6f);
    gv = ((const float4*)gk)[lane];
    st_h4(g_Kh + ((size_t)hh * LTOT + l) * HD + lane * 4,
          xv.x*inv*gv.x, xv.y*inv*gv.y, xv.z*inv*gv.z, xv.w*inv*gv.w);

    *(float4*)(g_Vall + ((size_t)hh * LTOT + l) * HD + lane * 4) = *(const float4*)(v + src);
}

__global__ void ipk_rms_kernel(const float* __restrict__ gipk) {
    int rid = blockIdx.x * 8 + (threadIdx.x >> 5);
    if (rid >= LIP * H) return;
    int lane = threadIdx.x & 31;
    int l = rid / H, hh = rid % H;
    float4 xv = *(const float4*)(g_ipk_raw + (size_t)l * DMOD + hh * HD + lane * 4);
    float inv = rsqrtf(warp_sum(xv.x*xv.x + xv.y*xv.y + xv.z*xv.z + xv.w*xv.w) / 128.f + 1e-6f);
    float4 gv = ((const float4*)gipk)[lane];
    st_h4(g_Kh + ((size_t)hh * LTOT + LIMG + l) * HD + lane * 4,
          xv.x*inv*gv.x, xv.y*inv*gv.y, xv.z*inv*gv.z, xv.w*inv*gv.w);
}

// ================= stage 4b: V transpose to fp16 [h][d][key] ================
__global__ void vt_kernel() {
    float* sm = (float*)dynsm;                  // [128 keys][133]
    int t = blockIdx.x, hh = blockIdx.y, tid = threadIdx.x;
    const float4* vsrc = (const float4*)(g_Vall + ((size_t)hh * LTOT + (size_t)t * 128) * HD);
    for (int i = tid; i < 128 * 32; i += 256) {
        int kr = i >> 5, d4 = i & 31;
        float4 f = vsrc[kr * 32 + d4];
        sm[kr * 133 + d4 * 4 + 0] = f.x;
        sm[kr * 133 + d4 * 4 + 1] = f.y;
        sm[kr * 133 + d4 * 4 + 2] = f.z;
        sm[kr * 133 + d4 * 4 + 3] = f.w;
    }
    __syncthreads();
    for (int j = 0; j < 8; j++) {
        int g = tid + j * 256;
        int d = g >> 4, kc = g & 15;
        float f[8];
#pragma unroll
        for (int i = 0; i < 8; i++) f[i] = sm[(kc * 8 + i) * 133 + d];
        uint4 u = { pkh(f[0], f[1]), pkh(f[2], f[3]), pkh(f[4], f[5]), pkh(f[6], f[7]) };
        *reinterpret_cast<uint4*>(g_Vth + ((size_t)hh * HD + d) * LTOT + (size_t)t * 128 + kc * 8) = u;
    }
}

// ================= stage 5: mma.sync flash attention (Br=64, 4 warps, 2 CTA/SM)
// SMEM: Q 64x272B | K 2 bufs of 64x272B | V 2 bufs of 128x144B = 89088 B
#define SQ_OFF  0
#define SK_OFF  17408
#define SK_BUF  17408
#define SV_OFF  (17408 + 2 * 17408)     // 52224
#define SV_BUF  18432
#define ATTN_SMEM (SV_OFF + 2 * SV_BUF) // 89088

__global__ void __launch_bounds__(128, 2) attn_kernel(float* __restrict__ out) {
    char* smem = dynsm;
    const uint32_t sb = s2u(smem);
    const int tid = threadIdx.x;
    const int w = tid >> 5, t = tid & 31;
    const int r4 = t >> 2, q4 = t & 3;
    const int hh = blockIdx.y, q0 = blockIdx.x * 64;

    const int rowselA = t & 15;
    const int winA = (t >> 4) << 4;
    const int rowselB = (t & 7) + ((t & 16) >> 1);
    const int winB = (t & 8) << 1;

    // ---- Q tile load: 64 rows x 16 chunks (row stride 272B) ----
    const uint4* qg = (const uint4*)(g_Qh + ((size_t)hh * LIMG + q0) * HD);
    for (int i = tid; i < 1024; i += 128) {
        int rr = i >> 4, cc = i & 15;
        *(uint4*)(smem + SQ_OFF + rr * 272 + cc * 16) = qg[i];
    }

    // ---- issue first 2 K/V tiles via cp.async ----
    const __half* kgb = g_Kh + (size_t)hh * LTOT * HD;
    const __half* vgb = g_Vth + (size_t)hh * HD * LTOT;
#pragma unroll
    for (int pb = 0; pb < 2; pb++) {
        for (int n = 0; n < 8; n++) {
            int i = tid + n * 128;
            int kr = i >> 4, c = i & 15;
            cp16(sb + SK_OFF + pb * SK_BUF + kr * 272 + c * 16,
                 kgb + ((size_t)(pb * KT + kr)) * HD + c * 8);
            int d = i >> 3, c2 = i & 7;
            cp16(sb + SV_OFF + pb * SV_BUF + d * 144 + c2 * 16,
                 vgb + (size_t)d * LTOT + pb * KT + c2 * 8);
        }
        asm volatile("cp.async.commit_group;");
    }
    __syncthreads();   // Q visible

    // ---- pinned Q fragments ----
    uint32_t qa[8][4];
#pragma unroll
    for (int kb = 0; kb < 8; kb++)
        ldsm4(qa[kb], sb + SQ_OFF + (w * 16 + rowselA) * 272 + kb * 32 + winA);

    float m_lo = -1e30f, m_hi = -1e30f;
    float oc[16][4];
#pragma unroll
    for (int n = 0; n < 16; n++)
#pragma unroll
        for (int j = 0; j < 4; j++) oc[n][j] = 0.f;
    float lacc[4] = {0.f, 0.f, 0.f, 0.f};     // row-sum accumulator (ones-MMA)

    for (int it = 0; it < NIT; it++) {
        const int b = it & 1;
        asm volatile("cp.async.wait_group 1;");
        __syncthreads();

        // ---- S = Q @ K^T ----
        float sc[8][4];
#pragma unroll
        for (int n = 0; n < 8; n++)
#pragma unroll
            for (int j = 0; j < 4; j++) sc[n][j] = 0.f;
        const uint32_t Kb = sb + SK_OFF + b * SK_BUF;
#pragma unroll
        for (int kb = 0; kb < 8; kb++) {
#pragma unroll
            for (int nbp = 0; nbp < 4; nbp++) {
                uint32_t bb[4];
                ldsm4(bb, Kb + (nbp * 16 + rowselB) * 272 + kb * 32 + winB);
                mma_f16(sc[2 * nbp],     qa[kb], bb[0], bb[1]);
                mma_f16(sc[2 * nbp + 1], qa[kb], bb[2], bb[3]);
            }
        }

        // ---- running max ----
        float mt_lo = -1e30f, mt_hi = -1e30f;
#pragma unroll
        for (int n = 0; n < 8; n++) {
            mt_lo = fmaxf(mt_lo, fmaxf(sc[n][0], sc[n][1]));
            mt_hi = fmaxf(mt_hi, fmaxf(sc[n][2], sc[n][3]));
        }
        mt_lo = fmaxf(mt_lo, __shfl_xor_sync(0xffffffffu, mt_lo, 1));
        mt_lo = fmaxf(mt_lo, __shfl_xor_sync(0xffffffffu, mt_lo, 2));
        mt_hi = fmaxf(mt_hi, __shfl_xor_sync(0xffffffffu, mt_hi, 1));
        mt_hi = fmaxf(mt_hi, __shfl_xor_sync(0xffffffffu, mt_hi, 2));
        float mn_lo = fmaxf(m_lo, mt_lo), mn_hi = fmaxf(m_hi, mt_hi);

        // ---- rescale only if max moved anywhere in the warp ----
        bool upd = (mn_lo > m_lo) | (mn_hi > m_hi);
        if (__any_sync(0xffffffffu, upd)) {
            float co_lo = ex2(m_lo - mn_lo), co_hi = ex2(m_hi - mn_hi);
#pragma unroll
            for (int n = 0; n < 16; n++) {
                oc[n][0] *= co_lo; oc[n][1] *= co_lo;
                oc[n][2] *= co_hi; oc[n][3] *= co_hi;
            }
            lacc[0] *= co_lo; lacc[1] *= co_lo;
            lacc[2] *= co_hi; lacc[3] *= co_hi;
        }
        m_lo = mn_lo; m_hi = mn_hi;

        // ---- P fragments: packed f16x2 exp2 ----
        uint32_t pa[4][4];
#pragma unroll
        for (int kb = 0; kb < 4; kb++) {
            pa[kb][0] = hex2(pk2(sc[2*kb][0]   - mn_lo, sc[2*kb][1]   - mn_lo));
            pa[kb][1] = hex2(pk2(sc[2*kb][2]   - mn_hi, sc[2*kb][3]   - mn_hi));
            pa[kb][2] = hex2(pk2(sc[2*kb+1][0] - mn_lo, sc[2*kb+1][1] - mn_lo));
            pa[kb][3] = hex2(pk2(sc[2*kb+1][2] - mn_hi, sc[2*kb+1][3] - mn_hi));
        }

        // ---- l += P @ ones (row sums) ----
#pragma unroll
        for (int kb = 0; kb < 4; kb++)
            mma_f16(lacc, pa[kb], ONES2, ONES2);

        // ---- O += P @ V ----
        const uint32_t Vb = sb + SV_OFF + b * SV_BUF;
#pragma unroll
        for (int kb = 0; kb < 4; kb++) {
#pragma unroll
            for (int nbp = 0; nbp < 8; nbp++) {
                uint32_t bb[4];
                ldsm4(bb, Vb + (nbp * 16 + rowselB) * 144 + kb * 32 + winB);
                mma_f16(oc[2 * nbp],     pa[kb], bb[0], bb[1]);
                mma_f16(oc[2 * nbp + 1], pa[kb], bb[2], bb[3]);
            }
        }
        __syncthreads();   // everyone done reading buf b

        // ---- refill buf b with tile it+2 (always commit to keep counts) ----
        if (it + 2 < NIT) {
            for (int n = 0; n < 8; n++) {
                int i = tid + n * 128;
                int kr = i >> 4, c = i & 15;
                cp16(sb + SK_OFF + b * SK_BUF + kr * 272 + c * 16,
                     kgb + ((size_t)((it + 2) * KT + kr)) * HD + c * 8);
                int d = i >> 3, c2 = i & 7;
                cp16(sb + SV_OFF + b * SV_BUF + d * 144 + c2 * 16,
                     vgb + (size_t)d * LTOT + (it + 2) * KT + c2 * 8);
            }
        }
        asm volatile("cp.async.commit_group;");
    }

    // ---- epilogue ----
    float il_lo = 1.f / lacc[0], il_hi = 1.f / lacc[2];
    float* orow_lo = out + (size_t)(q0 + w * 16 + r4) * DMOD + hh * HD + 2 * q4;
    float* orow_hi = orow_lo + (size_t)8 * DMOD;
#pragma unroll
    for (int nb = 0; nb < 16; nb++) {
        float2 vlo = { oc[nb][0] * il_lo, oc[nb][1] * il_lo };
        float2 vhi = { oc[nb][2] * il_hi, oc[nb][3] * il_hi };
        *(float2*)(orow_lo + nb * 8) = vlo;
        *(float2*)(orow_hi + nb * 8) = vhi;
    }
}

// ================= launch =====================================================
extern "C" void kernel_launch(void* const* d_in, const int* in_sizes, int n_in,
                              void* d_out, int out_size) {
    const float* ip   = (const float*)d_in[0];
    const float* q    = (const float*)d_in[1];
    const float* k    = (const float*)d_in[2];
    const float* v    = (const float*)d_in[3];
    const float* temb = (const float*)d_in[4];
    const float* wada = (const float*)d_in[5];
    const float* bada = (const float*)d_in[6];
    const float* wk   = (const float*)d_in[7];
    const float* wv   = (const float*)d_in[8];
    const float* gq   = (const float*)d_in[9];
    const float* gk   = (const float*)d_in[10];
    const float* gipk = (const float*)d_in[11];
    float* out = (float*)d_out;

    ada_kernel<<<(2 * DIP + 7) / 8, 256>>>(temb, wada, bada);
    adaln_kernel<<<LIP, 256>>>(ip);
    wconv_kernel<<<dim3(DMOD * DIP / 1024, 2), 256>>>(wk, wv);

    cudaFuncSetAttribute(ip_gemm_h_kernel, cudaFuncAttributeMaxDynamicSharedMemorySize, GEMM_SMEM);
    ip_gemm_h_kernel<<<dim3(DMOD * 2 / 192, LIP / 128), 256, GEMM_SMEM>>>();

    qkv_rms_kernel<<<(LIMG * H + 7) / 8, 256>>>(q, k, v, gq, gk);
    ipk_rms_kernel<<<(LIP * H + 7) / 8, 256>>>(gipk);

    cudaFuncSetAttribute(vt_kernel, cudaFuncAttributeMaxDynamicSharedMemorySize, 128 * 133 * 4);
    vt_kernel<<<dim3(LTOT / 128, H), 256, 128 * 133 * 4>>>();

    cudaFuncSetAttribute(attn_kernel, cudaFuncAttributeMaxDynamicSharedMemorySize, ATTN_SMEM);
    attn_kernel<<<dim3(LIMG / 64, H), 128, ATTN_SMEM>>>(out);
}

// round 11
// speedup vs baseline: 14.3961x; 1.0061x over previous
#include <cuda_runtime.h>
#include <cuda_fp16.h>
#include <math.h>
#include <stdint.h>

#define H     24
#define LIMG  2048
#define LIP   512
#define DMOD  3072
#define DIP   1280
#define HD    128
#define LTOT  2560
#define KT    64
#define NIT   (LTOT / KT)       // 40
// 1/sqrt(128) * log2(e)  (exp2-based softmax)
#define SCALE2 0.1275174735772347f
#define ONES2 0x3C003C00u       // half2(1.0, 1.0)

// ================= scratch =================
__device__ float  g_e[2 * DIP];
__device__ __half g_ipnorm_h[LIP * DIP];
__device__ __half g_Wh[2 * (size_t)DMOD * DIP];
__device__ float  g_ipk_raw[LIP * DMOD];
__device__ float  g_Vall[(size_t)H * LTOT * HD];         // fp32 head-major V
__device__ __half g_Qh[(size_t)H * LIMG * HD];           // pre-scaled fp16 Q
__device__ __half g_Kh[(size_t)H * LTOT * HD];           // fp16 K (img+ip)
__device__ __half g_Vth[(size_t)H * HD * LTOT];          // fp16 V transposed [h][d][key]

__device__ __forceinline__ uint32_t s2u(const void* p) {
    uint32_t a;
    asm("{ .reg .u64 t; cvta.to.shared.u64 t, %1; cvt.u32.u64 %0, t; }" : "=r"(a) : "l"(p));
    return a;
}
__device__ __forceinline__ uint32_t pkh(float a, float b) {
    __half2 h = __floats2half2_rn(a, b);
    return *reinterpret_cast<uint32_t*>(&h);
}
__device__ __forceinline__ uint32_t pk2(float lo, float hi) {
    uint32_t d;
    asm("cvt.rn.f16x2.f32 %0, %1, %2;" : "=r"(d) : "f"(hi), "f"(lo));
    return d;
}
__device__ __forceinline__ uint32_t hex2(uint32_t x) {
    uint32_t d;
    asm("ex2.approx.f16x2 %0, %1;" : "=r"(d) : "r"(x));
    return d;
}
__device__ __forceinline__ float ex2(float x) {
    float y;
    asm("ex2.approx.f32 %0, %1;" : "=f"(y) : "f"(x));
    return y;
}
__device__ __forceinline__ void mma_f16(float* c, const uint32_t* a, uint32_t b0, uint32_t b1) {
    asm volatile("mma.sync.aligned.m16n8k16.row.col.f32.f16.f16.f32 "
        "{%0,%1,%2,%3}, {%4,%5,%6,%7}, {%8,%9}, {%0,%1,%2,%3};"
        : "+f"(c[0]), "+f"(c[1]), "+f"(c[2]), "+f"(c[3])
        : "r"(a[0]), "r"(a[1]), "r"(a[2]), "r"(a[3]), "r"(b0), "r"(b1));
}
__device__ __forceinline__ void ldsm4(uint32_t* r, uint32_t addr) {
    asm volatile("ldmatrix.sync.aligned.m8n8.x4.shared.b16 {%0,%1,%2,%3}, [%4];"
        : "=r"(r[0]), "=r"(r[1]), "=r"(r[2]), "=r"(r[3]) : "r"(addr));
}
__device__ __forceinline__ void cp16(uint32_t dst, const void* src) {
    asm volatile("cp.async.cg.shared.global [%0], [%1], 16;" :: "r"(dst), "l"(src));
}

// single extern shared symbol for all dynamic-smem kernels
extern __shared__ __align__(16) char dynsm[];

// ================= stage 1: ada ================
__global__ void ada_kernel(const float* __restrict__ t_emb,
                           const float* __restrict__ w_ada,
                           const float* __restrict__ b_ada) {
    int o = blockIdx.x * 8 + (threadIdx.x >> 5);
    int lane = threadIdx.x & 31;
    if (o >= 2 * DIP) return;
    const float* w = w_ada + (size_t)o * DIP;
    float s = 0.f;
    for (int i = lane; i < DIP; i += 32) {
        float t = t_emb[i];
        s += (t / (1.f + expf(-t))) * w[i];
    }
#pragma unroll
    for (int off = 16; off; off >>= 1) s += __shfl_xor_sync(0xffffffffu, s, off);
    if (lane == 0) g_e[o] = s + b_ada[o];
}

// ================= stage 2: AdaLN -> fp16 ================
__global__ void adaln_kernel(const float* __restrict__ ip) {
    int row = blockIdx.x;
    const float* x = ip + (size_t)row * DIP;
    __shared__ float red1[8], red2[8];
    float s = 0.f, s2 = 0.f;
    for (int i = threadIdx.x; i < DIP; i += 256) {
        float v = x[i]; s += v; s2 += v * v;
    }
#pragma unroll
    for (int off = 16; off; off >>= 1) {
        s  += __shfl_xor_sync(0xffffffffu, s, off);
        s2 += __shfl_xor_sync(0xffffffffu, s2, off);
    }
    int w = threadIdx.x >> 5, lane = threadIdx.x & 31;
    if (lane == 0) { red1[w] = s; red2[w] = s2; }
    __syncthreads();
    float ts = 0.f, ts2 = 0.f;
#pragma unroll
    for (int i = 0; i < 8; i++) { ts += red1[i]; ts2 += red2[i]; }
    float mu = ts / DIP;
    float inv = rsqrtf(ts2 / DIP - mu * mu + 1e-6f);
    for (int i = threadIdx.x; i < DIP; i += 256) {
        float xn = (x[i] - mu) * inv;
        g_ipnorm_h[(size_t)row * DIP + i] = __float2half(xn * (1.f + g_e[DIP + i]) + g_e[i]);
    }
}

// ================= stage 2b: weight fp32 -> fp16 ================
__global__ void wconv_kernel(const float* __restrict__ wk, const float* __restrict__ wv) {
    size_t i = ((size_t)blockIdx.x * 256 + threadIdx.x) * 4;
    const float* src = blockIdx.y ? wv : wk;
    __half* dst = g_Wh + (size_t)blockIdx.y * DMOD * DIP;
    float4 f = *(const float4*)(src + i);
    uint2 u = { pkh(f.x, f.y), pkh(f.z, f.w) };
    *(uint2*)(dst + i) = u;
}

// ================= stage 3: fused ip GEMM (N = 6144) via mma.sync ============
#define GEMM_SMEM 92160

__device__ __forceinline__ void gemm_issue(uint32_t sb, int tid, int bm, int bn,
                                           int ks, int buf) {
#pragma unroll
    for (int n = 0; n < 4; n++) {
        int i = tid + n * 256;
        int row = i >> 3, c = i & 7;
        cp16(sb + buf * 18432 + row * 144 + c * 16,
             g_ipnorm_h + (size_t)(bm + row) * DIP + ks * 64 + c * 8);
    }
#pragma unroll
    for (int n = 0; n < 6; n++) {
        int i = tid + n * 256;
        int row = i >> 3, c = i & 7;
        cp16(sb + 36864 + buf * 27648 + row * 144 + c * 16,
             g_Wh + (size_t)(bn + row) * DIP + ks * 64 + c * 8);
    }
    asm volatile("cp.async.commit_group;");
}

__global__ void __launch_bounds__(256, 1) ip_gemm_h_kernel() {
    const uint32_t sb = s2u(dynsm);
    const int tid = threadIdx.x;
    const int w = tid >> 5, t = tid & 31;
    const int r4 = t >> 2, q4 = t & 3;
    const int bn = blockIdx.x * 192, bm = blockIdx.y * 128;

    gemm_issue(sb, tid, bm, bn, 0, 0);
    gemm_issue(sb, tid, bm, bn, 1, 1);

    float oc[24][4] = {};
    const int rowselA = t & 15;
    const int winA = (t >> 4) << 4;
    const int rowselB = (t & 7) + ((t & 16) >> 1);
    const int winB = (t & 8) << 1;

    for (int ks = 0; ks < 20; ks++) {
        const int buf = ks & 1;
        if (ks < 18) asm volatile("cp.async.wait_group 1;");
        else         asm volatile("cp.async.wait_group 0;");
        __syncthreads();
        const uint32_t Ab = sb + buf * 18432;
        const uint32_t Bb = sb + 36864 + buf * 27648;

        // batch all A-fragments (MLP=4)
        uint32_t aa[4][4];
#pragma unroll
        for (int kb = 0; kb < 4; kb++)
            ldsm4(aa[kb], Ab + (w * 16 + rowselA) * 144 + kb * 32 + winA);

        // depth-2 pipelined B-fragments over flattened (kb, nbp)
#define GADDR(s) (Bb + (((s) % 12) * 16 + rowselB) * 144 + ((s) / 12) * 32 + winB)
        uint32_t bb[3][4];
        ldsm4(bb[0], GADDR(0));
        ldsm4(bb[1], GADDR(1));
#pragma unroll
        for (int s = 0; s < 48; s++) {
            if (s + 2 < 48) ldsm4(bb[(s + 2) % 3], GADDR(s + 2));
            const int kb = s / 12, nbp = s % 12;
            mma_f16(oc[2 * nbp],     aa[kb], bb[s % 3][0], bb[s % 3][1]);
            mma_f16(oc[2 * nbp + 1], aa[kb], bb[s % 3][2], bb[s % 3][3]);
        }
#undef GADDR
        __syncthreads();
        if (ks + 2 < 20) gemm_issue(sb, tid, bm, bn, ks + 2, buf);
        else asm volatile("cp.async.commit_group;");
    }

    const int m_lo = bm + w * 16 + r4, m_hi = m_lo + 8;
#pragma unroll
    for (int nb = 0; nb < 24; nb++) {
        int n = bn + nb * 8 + q4 * 2;
        float2 vlo = { oc[nb][0], oc[nb][1] };
        float2 vhi = { oc[nb][2], oc[nb][3] };
        if (n < DMOD) {
            *(float2*)(g_ipk_raw + (size_t)m_lo * DMOD + n) = vlo;
            *(float2*)(g_ipk_raw + (size_t)m_hi * DMOD + n) = vhi;
        } else {
            int nn = n - DMOD;
            int hh = nn >> 7, dd = nn & 127;
            *(float2*)(g_Vall + ((size_t)hh * LTOT + LIMG + m_lo) * HD + dd) = vlo;
            *(float2*)(g_Vall + ((size_t)hh * LTOT + LIMG + m_hi) * HD + dd) = vhi;
        }
    }
}

// ================= stage 4: RMS + fp16 pack ================
__device__ __forceinline__ float warp_sum(float s) {
#pragma unroll
    for (int off = 16; off; off >>= 1) s += __shfl_xor_sync(0xffffffffu, s, off);
    return s;
}
__device__ __forceinline__ void st_h4(__half* p, float a, float b, float c, float d) {
    uint2 u = { pkh(a, b), pkh(c, d) };
    *reinterpret_cast<uint2*>(p) = u;
}

__global__ void qkv_rms_kernel(const float* __restrict__ q,
                               const float* __restrict__ k,
                               const float* __restrict__ v,
                               const float* __restrict__ gq,
                               const float* __restrict__ gk) {
    int rid = blockIdx.x * 8 + (threadIdx.x >> 5);
    if (rid >= LIMG * H) return;
    int lane = threadIdx.x & 31;
    int l = rid / H, hh = rid % H;
    size_t src = (size_t)l * DMOD + hh * HD + lane * 4;

    float4 xv = *(const float4*)(q + src);
    float inv = rsqrtf(warp_sum(xv.x*xv.x + xv.y*xv.y + xv.z*xv.z + xv.w*xv.w) / 128.f + 1e-6f) * SCALE2;
    float4 gv = ((const float4*)gq)[lane];
    st_h4(g_Qh + ((size_t)hh * LIMG + l) * HD + lane * 4,
          xv.x*inv*gv.x, xv.y*inv*gv.y, xv.z*inv*gv.z, xv.w*inv*gv.w);

    xv = *(const float4*)(k + src);
    inv = rsqrtf(warp_sum(xv.x*xv.x + xv.y*xv.y + xv.z*xv.z + xv.w*xv.w) / 128.f + 1e-6f);
    gv = ((const float4*)gk)[lane];
    st_h4(g_Kh + ((size_t)hh * LTOT + l) * HD + lane * 4,
          xv.x*inv*gv.x, xv.y*inv*gv.y, xv.z*inv*gv.z, xv.w*inv*gv.w);

    *(float4*)(g_Vall + ((size_t)hh * LTOT + l) * HD + lane * 4) = *(const float4*)(v + src);
}

__global__ void ipk_rms_kernel(const float* __restrict__ gipk) {
    int rid = blockIdx.x * 8 + (threadIdx.x >> 5);
    if (rid >= LIP * H) return;
    int lane = threadIdx.x & 31;
    int l = rid / H, hh = rid % H;
    float4 xv = *(const float4*)(g_ipk_raw + (size_t)l * DMOD + hh * HD + lane * 4);
    float inv = rsqrtf(warp_sum(xv.x*xv.x + xv.y*xv.y + xv.z*xv.z + xv.w*xv.w) / 128.f + 1e-6f);
    float4 gv = ((const float4*)gipk)[lane];
    st_h4(g_Kh + ((size_t)hh * LTOT + LIMG + l) * HD + lane * 4,
          xv.x*inv*gv.x, xv.y*inv*gv.y, xv.z*inv*gv.z, xv.w*inv*gv.w);
}

// ================= stage 4b: V transpose to fp16 [h][d][key] ================
__global__ void vt_kernel() {
    float* sm = (float*)dynsm;                  // [128 keys][133]
    int t = blockIdx.x, hh = blockIdx.y, tid = threadIdx.x;
    const float4* vsrc = (const float4*)(g_Vall + ((size_t)hh * LTOT + (size_t)t * 128) * HD);
    for (int i = tid; i < 128 * 32; i += 256) {
        int kr = i >> 5, d4 = i & 31;
        float4 f = vsrc[kr * 32 + d4];
        sm[kr * 133 + d4 * 4 + 0] = f.x;
        sm[kr * 133 + d4 * 4 + 1] = f.y;
        sm[kr * 133 + d4 * 4 + 2] = f.z;
        sm[kr * 133 + d4 * 4 + 3] = f.w;
    }
    __syncthreads();
    for (int j = 0; j < 8; j++) {
        int g = tid + j * 256;
        int d = g >> 4, kc = g & 15;
        float f[8];
#pragma unroll
        for (int i = 0; i < 8; i++) f[i] = sm[(kc * 8 + i) * 133 + d];
        uint4 u = { pkh(f[0], f[1]), pkh(f[2], f[3]), pkh(f[4], f[5]), pkh(f[6], f[7]) };
        *reinterpret_cast<uint4*>(g_Vth + ((size_t)hh * HD + d) * LTOT + (size_t)t * 128 + kc * 8) = u;
    }
}

// ================= stage 5: mma.sync flash attention (Br=64, 4 warps, 2 CTA/SM)
// SMEM: Q 64x272B | K 2 bufs of 64x272B | V 2 bufs of 128x144B = 89088 B
#define SQ_OFF  0
#define SK_OFF  17408
#define SK_BUF  17408
#define SV_OFF  (17408 + 2 * 17408)     // 52224
#define SV_BUF  18432
#define ATTN_SMEM (SV_OFF + 2 * SV_BUF) // 89088

__global__ void __launch_bounds__(128, 2) attn_kernel(float* __restrict__ out) {
    char* smem = dynsm;
    const uint32_t sb = s2u(smem);
    const int tid = threadIdx.x;
    const int w = tid >> 5, t = tid & 31;
    const int r4 = t >> 2, q4 = t & 3;
    const int hh = blockIdx.y, q0 = blockIdx.x * 64;

    const int rowselA = t & 15;
    const int winA = (t >> 4) << 4;
    const int rowselB = (t & 7) + ((t & 16) >> 1);
    const int winB = (t & 8) << 1;

    // ---- Q tile load: 64 rows x 16 chunks (row stride 272B) ----
    const uint4* qg = (const uint4*)(g_Qh + ((size_t)hh * LIMG + q0) * HD);
    for (int i = tid; i < 1024; i += 128) {
        int rr = i >> 4, cc = i & 15;
        *(uint4*)(smem + SQ_OFF + rr * 272 + cc * 16) = qg[i];
    }

    // ---- issue first 2 K/V tiles via cp.async ----
    const __half* kgb = g_Kh + (size_t)hh * LTOT * HD;
    const __half* vgb = g_Vth + (size_t)hh * HD * LTOT;
#pragma unroll
    for (int pb = 0; pb < 2; pb++) {
        for (int n = 0; n < 8; n++) {
            int i = tid + n * 128;
            int kr = i >> 4, c = i & 15;
            cp16(sb + SK_OFF + pb * SK_BUF + kr * 272 + c * 16,
                 kgb + ((size_t)(pb * KT + kr)) * HD + c * 8);
            int d = i >> 3, c2 = i & 7;
            cp16(sb + SV_OFF + pb * SV_BUF + d * 144 + c2 * 16,
                 vgb + (size_t)d * LTOT + pb * KT + c2 * 8);
        }
        asm volatile("cp.async.commit_group;");
    }
    __syncthreads();   // Q visible

    // ---- pinned Q fragments ----
    uint32_t qa[8][4];
#pragma unroll
    for (int kb = 0; kb < 8; kb++)
        ldsm4(qa[kb], sb + SQ_OFF + (w * 16 + rowselA) * 272 + kb * 32 + winA);

    float m_lo = -1e30f, m_hi = -1e30f;
    float oc[16][4];
#pragma unroll
    for (int n = 0; n < 16; n++)
#pragma unroll
        for (int j = 0; j < 4; j++) oc[n][j] = 0.f;
    float lacc[4] = {0.f, 0.f, 0.f, 0.f};     // row-sum accumulator (ones-MMA)

    for (int it = 0; it < NIT; it++) {
        const int b = it & 1;
        asm volatile("cp.async.wait_group 1;");
        __syncthreads();

        // ---- S = Q @ K^T : depth-2 pipelined B-fragments ----
        float sc[8][4];
#pragma unroll
        for (int n = 0; n < 8; n++)
#pragma unroll
            for (int j = 0; j < 4; j++) sc[n][j] = 0.f;
        const uint32_t Kb = sb + SK_OFF + b * SK_BUF;
#define KADDR(s) (Kb + (((s) & 3) * 16 + rowselB) * 272 + ((s) >> 2) * 32 + winB)
        {
            uint32_t bb[3][4];
            ldsm4(bb[0], KADDR(0));
            ldsm4(bb[1], KADDR(1));
#pragma unroll
            for (int s = 0; s < 32; s++) {
                if (s + 2 < 32) ldsm4(bb[(s + 2) % 3], KADDR(s + 2));
                const int kb = s >> 2, nbp = s & 3;
                mma_f16(sc[2 * nbp],     qa[kb], bb[s % 3][0], bb[s % 3][1]);
                mma_f16(sc[2 * nbp + 1], qa[kb], bb[s % 3][2], bb[s % 3][3]);
            }
        }
#undef KADDR

        // ---- running max ----
        float mt_lo = -1e30f, mt_hi = -1e30f;
#pragma unroll
        for (int n = 0; n < 8; n++) {
            mt_lo = fmaxf(mt_lo, fmaxf(sc[n][0], sc[n][1]));
            mt_hi = fmaxf(mt_hi, fmaxf(sc[n][2], sc[n][3]));
        }
        mt_lo = fmaxf(mt_lo, __shfl_xor_sync(0xffffffffu, mt_lo, 1));
        mt_lo = fmaxf(mt_lo, __shfl_xor_sync(0xffffffffu, mt_lo, 2));
        mt_hi = fmaxf(mt_hi, __shfl_xor_sync(0xffffffffu, mt_hi, 1));
        mt_hi = fmaxf(mt_hi, __shfl_xor_sync(0xffffffffu, mt_hi, 2));
        float mn_lo = fmaxf(m_lo, mt_lo), mn_hi = fmaxf(m_hi, mt_hi);

        // ---- rescale only if max moved anywhere in the warp ----
        bool upd = (mn_lo > m_lo) | (mn_hi > m_hi);
        if (__any_sync(0xffffffffu, upd)) {
            float co_lo = ex2(m_lo - mn_lo), co_hi = ex2(m_hi - mn_hi);
#pragma unroll
            for (int n = 0; n < 16; n++) {
                oc[n][0] *= co_lo; oc[n][1] *= co_lo;
                oc[n][2] *= co_hi; oc[n][3] *= co_hi;
            }
            lacc[0] *= co_lo; lacc[1] *= co_lo;
            lacc[2] *= co_hi; lacc[3] *= co_hi;
        }
        m_lo = mn_lo; m_hi = mn_hi;

        // ---- P fragments: packed f16x2 exp2 ----
        uint32_t pa[4][4];
#pragma unroll
        for (int kb = 0; kb < 4; kb++) {
            pa[kb][0] = hex2(pk2(sc[2*kb][0]   - mn_lo, sc[2*kb][1]   - mn_lo));
            pa[kb][1] = hex2(pk2(sc[2*kb][2]   - mn_hi, sc[2*kb][3]   - mn_hi));
            pa[kb][2] = hex2(pk2(sc[2*kb+1][0] - mn_lo, sc[2*kb+1][1] - mn_lo));
            pa[kb][3] = hex2(pk2(sc[2*kb+1][2] - mn_hi, sc[2*kb+1][3] - mn_hi));
        }

        // ---- l += P @ ones (row sums) ----
#pragma unroll
        for (int kb = 0; kb < 4; kb++)
            mma_f16(lacc, pa[kb], ONES2, ONES2);

        // ---- O += P @ V : depth-2 pipelined B-fragments ----
        const uint32_t Vb = sb + SV_OFF + b * SV_BUF;
#define VADDR(s) (Vb + (((s) & 7) * 16 + rowselB) * 144 + ((s) >> 3) * 32 + winB)
        {
            uint32_t bb[3][4];
            ldsm4(bb[0], VADDR(0));
            ldsm4(bb[1], VADDR(1));
#pragma unroll
            for (int s = 0; s < 32; s++) {
                if (s + 2 < 32) ldsm4(bb[(s + 2) % 3], VADDR(s + 2));
                const int kb = s >> 3, nbp = s & 7;
                mma_f16(oc[2 * nbp],     pa[kb], bb[s % 3][0], bb[s % 3][1]);
                mma_f16(oc[2 * nbp + 1], pa[kb], bb[s % 3][2], bb[s % 3][3]);
            }
        }
#undef VADDR
        __syncthreads();   // everyone done reading buf b

        // ---- refill buf b with tile it+2 (always commit to keep counts) ----
        if (it + 2 < NIT) {
            for (int n = 0; n < 8; n++) {
                int i = tid + n * 128;
                int kr = i >> 4, c = i & 15;
                cp16(sb + SK_OFF + b * SK_BUF + kr * 272 + c * 16,
                     kgb + ((size_t)((it + 2) * KT + kr)) * HD + c * 8);
                int d = i >> 3, c2 = i & 7;
                cp16(sb + SV_OFF + b * SV_BUF + d * 144 + c2 * 16,
                     vgb + (size_t)d * LTOT + (it + 2) * KT + c2 * 8);
            }
        }
        asm volatile("cp.async.commit_group;");
    }

    // ---- epilogue ----
    float il_lo = 1.f / lacc[0], il_hi = 1.f / lacc[2];
    float* orow_lo = out + (size_t)(q0 + w * 16 + r4) * DMOD + hh * HD + 2 * q4;
    float* orow_hi = orow_lo + (size_t)8 * DMOD;
#pragma unroll
    for (int nb = 0; nb < 16; nb++) {
        float2 vlo = { oc[nb][0] * il_lo, oc[nb][1] * il_lo };
        float2 vhi = { oc[nb][2] * il_hi, oc[nb][3] * il_hi };
        *(float2*)(orow_lo + nb * 8) = vlo;
        *(float2*)(orow_hi + nb * 8) = vhi;
    }
}

// ================= launch =====================================================
extern "C" void kernel_launch(void* const* d_in, const int* in_sizes, int n_in,
                              void* d_out, int out_size) {
    const float* ip   = (const float*)d_in[0];
    const float* q    = (const float*)d_in[1];
    const float* k    = (const float*)d_in[2];
    const float* v    = (const float*)d_in[3];
    const float* temb = (const float*)d_in[4];
    const float* wada = (const float*)d_in[5];
    const float* bada = (const float*)d_in[6];
    const float* wk   = (const float*)d_in[7];
    const float* wv   = (const float*)d_in[8];
    const float* gq   = (const float*)d_in[9];
    const float* gk   = (const float*)d_in[10];
    const float* gipk = (const float*)d_in[11];
    float* out = (float*)d_out;

    ada_kernel<<<(2 * DIP + 7) / 8, 256>>>(temb, wada, bada);
    adaln_kernel<<<LIP, 256>>>(ip);
    wconv_kernel<<<dim3(DMOD * DIP / 1024, 2), 256>>>(wk, wv);

    cudaFuncSetAttribute(ip_gemm_h_kernel, cudaFuncAttributeMaxDynamicSharedMemorySize, GEMM_SMEM);
    ip_gemm_h_kernel<<<dim3(DMOD * 2 / 192, LIP / 128), 256, GEMM_SMEM>>>();

    qkv_rms_kernel<<<(LIMG * H + 7) / 8, 256>>>(q, k, v, gq, gk);
    ipk_rms_kernel<<<(LIP * H + 7) / 8, 256>>>(gipk);

    cudaFuncSetAttribute(vt_kernel, cudaFuncAttributeMaxDynamicSharedMemorySize, 128 * 133 * 4);
    vt_kernel<<<dim3(LTOT / 128, H), 256, 128 * 133 * 4>>>();

    cudaFuncSetAttribute(attn_kernel, cudaFuncAttributeMaxDynamicSharedMemorySize, ATTN_SMEM);
    attn_kernel<<<dim3(LIMG / 64, H), 128, ATTN_SMEM>>>(out);
}